// round 7
// baseline (speedup 1.0000x reference)
#include <cuda_runtime.h>
#include <cuda_bf16.h>
#include <math.h>

#define N 16384
#define D 256
#define T 128

typedef unsigned int u32;
typedef unsigned long long u64;

// ---------------- scratch ---------------------------------------------------
__device__ float g_V[T * D];        // gathered token embeddings fp32 [t][d]
__device__ u32   g_Vh[T * 128];     // V hi split bf16x2 [t][k/2]
__device__ u32   g_Vl[T * 128];     // V lo split
__device__ u32   g_XTh[N * 64];     // X^T hi split, bf16x2 [n][t/2]
__device__ u32   g_XTl[N * 64];     // X^T lo split
__device__ u32   g_cVh[D * 64];     // (0.97^(T-s)*V[s][d]) hi split, [d][s/2]
__device__ u32   g_cVl[D * 64];
__device__ float g_part2[128 * T];  // dot partials [block][s]
__device__ float g_lnA[D];
__device__ float g_u[D];

// ---------------- helpers ----------------------------------------------------
__device__ __forceinline__ u32 s2u(const void* p) {
    u32 a;
    asm("{ .reg .u64 t; cvta.to.shared.u64 t, %1; cvt.u32.u64 %0, t; }" : "=r"(a) : "l"(p));
    return a;
}
__device__ __forceinline__ u32 pack_bf16(float lo, float hi) {
    u32 r;
    asm("cvt.rn.bf16x2.f32 %0, %1, %2;" : "=r"(r) : "f"(hi), "f"(lo));
    return r;
}

#define LDSM_X4(r, addr)                                                        \
    asm volatile(                                                               \
        "ldmatrix.sync.aligned.m8n8.x4.shared.b16 {%0,%1,%2,%3}, [%4];"         \
        : "=r"((r)[0]), "=r"((r)[1]), "=r"((r)[2]), "=r"((r)[3])                \
        : "r"(addr))

__device__ __forceinline__ void mma16816(float* c, const u32* a, u32 b0, u32 b1) {
    asm volatile(
        "mma.sync.aligned.m16n8k16.row.col.f32.bf16.bf16.f32 "
        "{%0,%1,%2,%3}, {%4,%5,%6,%7}, {%8,%9}, {%0,%1,%2,%3};"
        : "+f"(c[0]), "+f"(c[1]), "+f"(c[2]), "+f"(c[3])
        : "r"(a[0]), "r"(a[1]), "r"(a[2]), "r"(a[3]), "r"(b0), "r"(b1));
}

// split float4 -> hi u64 (2 bf16x2) + lo u64
__device__ __forceinline__ void split4(float4 v, u64& hp, u64& lp) {
    u32 h0 = pack_bf16(v.x, v.y);
    u32 h1 = pack_bf16(v.z, v.w);
    u32 l0 = pack_bf16(v.x - __uint_as_float(h0 << 16),
                       v.y - __uint_as_float(h0 & 0xFFFF0000u));
    u32 l1 = pack_bf16(v.z - __uint_as_float(h1 << 16),
                       v.w - __uint_as_float(h1 & 0xFFFF0000u));
    hp = ((u64)h1 << 32) | h0;
    lp = ((u64)l1 << 32) | l0;
}

// ---------------- K1: gather + V splits --------------------------------------
__global__ __launch_bounds__(256) void k_gather_prep(const float* __restrict__ temb,
                                                     const int* __restrict__ toks) {
    int t = blockIdx.x, tid = threadIdx.x;
    g_V[t * D + tid] = temb[(size_t)toks[t] * D + tid];
    __syncthreads();
    if (tid < 128) {
        float v0 = g_V[t * D + 2 * tid];
        float v1 = g_V[t * D + 2 * tid + 1];
        u32 h = pack_bf16(v0, v1);
        u32 l = pack_bf16(v0 - __uint_as_float(h << 16),
                          v1 - __uint_as_float(h & 0xFFFF0000u));
        g_Vh[t * 128 + tid] = h;
        g_Vl[t * 128 + tid] = l;
    }
}

// ---------------- K2: cV splits ----------------------------------------------
__global__ void k_prep_cv() {
    int d = blockIdx.x;
    int s2 = threadIdx.x;  // 64 threads: s pair
    int s0 = 2 * s2, s1 = s0 + 1;
    float c0 = (float)pow(0.97, (double)(T - s0));
    float c1 = (float)pow(0.97, (double)(T - s1));
    float a0 = c0 * g_V[s0 * D + d];
    float a1 = c1 * g_V[s1 * D + d];
    u32 h = pack_bf16(a0, a1);
    u32 l = pack_bf16(a0 - __uint_as_float(h << 16), a1 - __uint_as_float(h & 0xFFFF0000u));
    g_cVh[d * 64 + s2] = h;
    g_cVl[d * 64 + s2] = l;
}

// ---------------- K3: GEMM1 (mma.sync, 512 thr, 32x32 warp tiles) ------------
// C[n][t] = sum_k Dx[n][k]*V[t][k]; epilogue: relu+cumsum, XT splits, partials.
#define PA1 36  // word pitch for [128][32w] tiles
__global__ __launch_bounds__(512) void k_gemm1(const float* __restrict__ Dx,
                                               float* __restrict__ out) {
    extern __shared__ char sm[];
    const int S_AH = 0, S_AL = 18432, S_BH = 36864, S_BL = 55296;
    int tid = threadIdx.x;
    int lane = tid & 31, wid = tid >> 5;  // wid 0..15
    int gr = lane >> 2, gc = lane & 3;
    int r8 = lane & 7, sub = lane >> 3;
    int m0w = (wid & 3) * 32;   // n rows
    int t0 = (wid >> 2) * 32;   // t cols
    int n0 = blockIdx.x * 128;
    u32 smb = s2u(sm);

    float acc[2][4][4];
#pragma unroll
    for (int i = 0; i < 2; i++)
#pragma unroll
        for (int j = 0; j < 4; j++)
#pragma unroll
            for (int q = 0; q < 4; q++) acc[i][j][q] = 0.f;

    // prefetch chunk 0 of Dx (4 float4/thread)
    float4 pa[4];
#pragma unroll
    for (int r = 0; r < 4; r++) {
        int gi = tid + 512 * r;
        int row = gi >> 4, f4 = gi & 15;
        pa[r] = *(const float4*)&Dx[(size_t)(n0 + row) * D + f4 * 4];
    }

    for (int c = 0; c < 4; c++) {  // K chunks of 64
#pragma unroll
        for (int r = 0; r < 4; r++) {
            int gi = tid + 512 * r;
            int row = gi >> 4, f4 = gi & 15;
            u64 hp, lp;
            split4(pa[r], hp, lp);
            *(u64*)(sm + S_AH + row * (PA1 * 4) + f4 * 8) = hp;
            *(u64*)(sm + S_AL + row * (PA1 * 4) + f4 * 8) = lp;
        }
#pragma unroll
        for (int r = 0; r < 2; r++) {
            int gi = tid + 512 * r;  // 1024 uint4 per split
            int row = gi >> 3, j4 = gi & 7;
            *(uint4*)(sm + S_BH + row * (PA1 * 4) + j4 * 16) =
                ((const uint4*)g_Vh)[row * 32 + c * 8 + j4];
            *(uint4*)(sm + S_BL + row * (PA1 * 4) + j4 * 16) =
                ((const uint4*)g_Vl)[row * 32 + c * 8 + j4];
        }
        __syncthreads();
        if (c < 3) {
#pragma unroll
            for (int r = 0; r < 4; r++) {
                int gi = tid + 512 * r;
                int row = gi >> 4, f4 = gi & 15;
                pa[r] = *(const float4*)&Dx[(size_t)(n0 + row) * D + (c + 1) * 64 + f4 * 4];
            }
        }
#pragma unroll
        for (int ks = 0; ks < 4; ks++) {
            u32 ah[2][4], al[2][4], bh[2][4], bl[2][4];
#pragma unroll
            for (int mt = 0; mt < 2; mt++) {
                int aw = (m0w + mt * 16 + r8 + (sub & 1) * 8) * PA1 + (sub >> 1) * 4 + ks * 8;
                LDSM_X4(ah[mt], smb + S_AH + aw * 4);
                LDSM_X4(al[mt], smb + S_AL + aw * 4);
            }
#pragma unroll
            for (int g = 0; g < 2; g++) {
                int bw = (t0 + g * 16 + r8 + (sub >> 1) * 8) * PA1 + (sub & 1) * 4 + ks * 8;
                LDSM_X4(bh[g], smb + S_BH + bw * 4);
                LDSM_X4(bl[g], smb + S_BL + bw * 4);
            }
            // pass 1: ah*bh (8 MMAs, all-distinct accs)
#pragma unroll
            for (int g = 0; g < 2; g++)
#pragma unroll
                for (int mt = 0; mt < 2; mt++) {
                    mma16816(acc[mt][2 * g], ah[mt], bh[g][0], bh[g][1]);
                    mma16816(acc[mt][2 * g + 1], ah[mt], bh[g][2], bh[g][3]);
                }
            // pass 2: ah*bl
#pragma unroll
            for (int g = 0; g < 2; g++)
#pragma unroll
                for (int mt = 0; mt < 2; mt++) {
                    mma16816(acc[mt][2 * g], ah[mt], bl[g][0], bl[g][1]);
                    mma16816(acc[mt][2 * g + 1], ah[mt], bl[g][2], bl[g][3]);
                }
            // pass 3: al*bh
#pragma unroll
            for (int g = 0; g < 2; g++)
#pragma unroll
                for (int mt = 0; mt < 2; mt++) {
                    mma16816(acc[mt][2 * g], al[mt], bh[g][0], bh[g][1]);
                    mma16816(acc[mt][2 * g + 1], al[mt], bh[g][2], bh[g][3]);
                }
        }
        __syncthreads();
    }

    // ---- epilogue: relu -> Xs[128][130], 4-segment cumsum, splits, partials --
    float* Xs = (float*)sm;
    float* sx = (float*)(sm + 66560);           // [128] x_f
    float* tot = (float*)(sm + 67072);          // [128][4] segment totals
#pragma unroll
    for (int mt = 0; mt < 2; mt++)
#pragma unroll
        for (int j = 0; j < 4; j++) {
            int row = m0w + mt * 16 + gr;
            int col = t0 + j * 8 + 2 * gc;
            *(float2*)&Xs[row * 130 + col] =
                make_float2(fmaxf(acc[mt][j][0], 0.f), fmaxf(acc[mt][j][1], 0.f));
            *(float2*)&Xs[(row + 8) * 130 + col] =
                make_float2(fmaxf(acc[mt][j][2], 0.f), fmaxf(acc[mt][j][3], 0.f));
        }
    __syncthreads();
    {
        int n = tid & 127, q = tid >> 7;  // 4 t-segments of 32
        float v[32];
        float a = 0.f;
#pragma unroll
        for (int i = 0; i < 16; i++) {
            float2 p = *(float2*)&Xs[n * 130 + q * 32 + 2 * i];
            a += p.x;
            v[2 * i] = a;
            a += p.y;
            v[2 * i + 1] = a;
        }
        tot[n * 4 + q] = a;
        __syncthreads();
        float off = 0.f;
#pragma unroll
        for (int qq = 0; qq < 3; qq++)
            if (qq < q) off += tot[n * 4 + qq];
#pragma unroll
        for (int p = 0; p < 16; p++) {
            float x0 = v[2 * p] + off, x1 = v[2 * p + 1] + off;
            *(float2*)&Xs[n * 130 + q * 32 + 2 * p] = make_float2(x0, x1);
            u32 hh = pack_bf16(x0, x1);
            u32 ll = pack_bf16(x0 - __uint_as_float(hh << 16),
                               x1 - __uint_as_float(hh & 0xFFFF0000u));
            g_XTh[(size_t)(n0 + n) * 64 + q * 16 + p] = hh;
            g_XTl[(size_t)(n0 + n) * 64 + q * 16 + p] = ll;
        }
        if (q == 3) {
            float xf = v[31] + off;
            out[n0 + n] = xf;
            sx[n] = xf;
        }
    }
    __syncthreads();
    {
        int t = tid & 127, q = tid >> 7;  // 4 n-segments of 32
        float s = 0.f;
#pragma unroll 8
        for (int n2 = q * 32; n2 < q * 32 + 32; n2++)
            s = fmaf(Xs[n2 * 130 + t], sx[n2], s);
        tot[t * 4 + q] = s;
    }
    __syncthreads();
    if (tid < 128)
        g_part2[blockIdx.x * 128 + tid] =
            (tot[tid * 4] + tot[tid * 4 + 1]) + (tot[tid * 4 + 2] + tot[tid * 4 + 3]);
}

// ---------------- K4: GEMM2 (mma.sync, 32x64 warp tiles, pass-reordered) -----
// C[d][n] = sum_s cV[d][s]*XT[n][s]; coalesced float2 stores to rho[d][n].
#define PA2 68  // word pitch for [*][64w] tiles
__global__ __launch_bounds__(512) void k_gemm2(float* __restrict__ out) {
    extern __shared__ char sm[];
    const int S_AH = 0, S_AL = 69632, S_BH = 139264, S_BL = 174080;
    int tid = threadIdx.x;
    int lane = tid & 31, wid = tid >> 5;  // wid 0..15
    int gr = lane >> 2, gc = lane & 3;
    int r8 = lane & 7, sub = lane >> 3;
    int m0w = (wid & 7) * 32;   // d rows
    int nb = (wid >> 3) * 64;   // n cols within tile
    int n0 = blockIdx.x * 128;
    u32 smb = s2u(sm);

#pragma unroll
    for (int r = 0; r < 8; r++) {
        int gi = tid + 512 * r;  // 4096 uint4
        int row = gi >> 4, j4 = gi & 15;
        *(uint4*)(sm + S_AH + row * (PA2 * 4) + j4 * 16) =
            ((const uint4*)g_cVh)[row * 16 + j4];
        *(uint4*)(sm + S_AL + row * (PA2 * 4) + j4 * 16) =
            ((const uint4*)g_cVl)[row * 16 + j4];
    }
#pragma unroll
    for (int r = 0; r < 4; r++) {
        int gi = tid + 512 * r;  // 2048 uint4
        int row = gi >> 4, j4 = gi & 15;
        *(uint4*)(sm + S_BH + row * (PA2 * 4) + j4 * 16) =
            ((const uint4*)g_XTh)[(size_t)(n0 + row) * 16 + j4];
        *(uint4*)(sm + S_BL + row * (PA2 * 4) + j4 * 16) =
            ((const uint4*)g_XTl)[(size_t)(n0 + row) * 16 + j4];
    }
    __syncthreads();

    float acc[2][8][4];
#pragma unroll
    for (int i = 0; i < 2; i++)
#pragma unroll
        for (int j = 0; j < 8; j++)
#pragma unroll
            for (int q = 0; q < 4; q++) acc[i][j][q] = 0.f;

#pragma unroll
    for (int ks = 0; ks < 8; ks++) {
        u32 ah[2][4], al[2][4];
#pragma unroll
        for (int mt = 0; mt < 2; mt++) {
            int aw = (m0w + mt * 16 + r8 + (sub & 1) * 8) * PA2 + (sub >> 1) * 4 + ks * 8;
            LDSM_X4(ah[mt], smb + S_AH + aw * 4);
            LDSM_X4(al[mt], smb + S_AL + aw * 4);
        }
#pragma unroll
        for (int g = 0; g < 4; g++) {
            u32 bh[4], bl[4];
            int bw = (nb + g * 16 + r8 + (sub >> 1) * 8) * PA2 + (sub & 1) * 4 + ks * 8;
            LDSM_X4(bh, smb + S_BH + bw * 4);
            LDSM_X4(bl, smb + S_BL + bw * 4);
            // pass-reordered: same-acc spacing of 4
            mma16816(acc[0][2 * g], ah[0], bh[0], bh[1]);
            mma16816(acc[1][2 * g], ah[1], bh[0], bh[1]);
            mma16816(acc[0][2 * g + 1], ah[0], bh[2], bh[3]);
            mma16816(acc[1][2 * g + 1], ah[1], bh[2], bh[3]);
            mma16816(acc[0][2 * g], ah[0], bl[0], bl[1]);
            mma16816(acc[1][2 * g], ah[1], bl[0], bl[1]);
            mma16816(acc[0][2 * g + 1], ah[0], bl[2], bl[3]);
            mma16816(acc[1][2 * g + 1], ah[1], bl[2], bl[3]);
            mma16816(acc[0][2 * g], al[0], bh[0], bh[1]);
            mma16816(acc[1][2 * g], al[1], bh[0], bh[1]);
            mma16816(acc[0][2 * g + 1], al[0], bh[2], bh[3]);
            mma16816(acc[1][2 * g + 1], al[1], bh[2], bh[3]);
        }
    }

    float* rho = out + 2 * N + D;
#pragma unroll
    for (int mt = 0; mt < 2; mt++)
#pragma unroll
        for (int j = 0; j < 8; j++) {
            int d = m0w + mt * 16 + gr;
            int col = n0 + nb + j * 8 + 2 * gc;
            *(float2*)&rho[(size_t)d * N + col] = make_float2(acc[mt][j][0], acc[mt][j][1]);
            *(float2*)&rho[(size_t)(d + 8) * N + col] = make_float2(acc[mt][j][2], acc[mt][j][3]);
        }
}

// ---------------- K5: a*[d] -> layernorm -> g_lnA ----------------------------
__global__ void k_astar_ln() {
    __shared__ float gg[T];
    __shared__ float red[256];
    int tid = threadIdx.x;  // = d
    if (tid < T) {
        float s = 0.f;
        for (int b = 0; b < 128; b++) s += g_part2[b * 128 + tid];
        gg[tid] = (tid < T - 1) ? (float)pow(0.97, (double)(T - 1 - tid)) * s : 0.f;
    }
    __syncthreads();
    float a = 0.f;
    for (int s = 0; s < T - 1; s++) a = fmaf(gg[s], g_V[s * D + tid], a);
    red[tid] = a;
    __syncthreads();
    for (int off = 128; off > 0; off >>= 1) {
        if (tid < off) red[tid] += red[tid + off];
        __syncthreads();
    }
    float m = red[0] * (1.f / D);
    __syncthreads();
    float ctr = a - m;
    red[tid] = ctr * ctr;
    __syncthreads();
    for (int off = 128; off > 0; off >>= 1) {
        if (tid < off) red[tid] += red[tid + off];
        __syncthreads();
    }
    float sd = sqrtf(red[0] / (float)(D - 1));
    g_lnA[tid] = ctr / (sd + 1e-6f);
}

// ---------------- K6: y[n] = relu(Dy.lnA) * relu(x_f) -> out[N:2N) ----------
__global__ void k_y(const float* __restrict__ Dy, float* __restrict__ out) {
    __shared__ float sa[D];
    int tid = threadIdx.x;
    sa[tid] = g_lnA[tid];
    __syncthreads();
    int warp = tid >> 5, lane = tid & 31;
    int n = blockIdx.x * 8 + warp;
    const float4* row = (const float4*)&Dy[(size_t)n * D];
    float s = 0.f;
#pragma unroll
    for (int r = 0; r < 2; r++) {
        float4 v = row[lane + 32 * r];
        int d = 4 * (lane + 32 * r);
        s = fmaf(v.x, sa[d], s);
        s = fmaf(v.y, sa[d + 1], s);
        s = fmaf(v.z, sa[d + 2], s);
        s = fmaf(v.w, sa[d + 3], s);
    }
#pragma unroll
    for (int off = 16; off > 0; off >>= 1) s += __shfl_down_sync(0xffffffffu, s, off);
    if (lane == 0) out[N + n] = fmaxf(s, 0.f) * fmaxf(out[n], 0.f);
}

// ---------------- K7: u[d] = E[d,:].y ---------------------------------------
__global__ void k_u(const float* __restrict__ E, const float* __restrict__ out) {
    __shared__ float red[256];
    int d = blockIdx.x, tid = threadIdx.x;
    const float4* e = (const float4*)&E[(size_t)d * N];
    const float4* y = (const float4*)&out[N];
    float s = 0.f;
#pragma unroll 4
    for (int r = 0; r < 16; r++) {
        float4 a = e[tid + 256 * r];
        float4 b = y[tid + 256 * r];
        s = fmaf(a.x, b.x, s);
        s = fmaf(a.y, b.y, s);
        s = fmaf(a.z, b.z, s);
        s = fmaf(a.w, b.w, s);
    }
    red[tid] = s;
    __syncthreads();
    for (int off = 128; off > 0; off >>= 1) {
        if (tid < off) red[tid] += red[tid + off];
        __syncthreads();
    }
    if (tid == 0) g_u[d] = red[0];
}

// ---------------- K8: v* = layernorm(u) -> out[2N:2N+D) ---------------------
__global__ void k_vstar(float* __restrict__ out) {
    __shared__ float red[256];
    int tid = threadIdx.x;
    float a = g_u[tid];
    red[tid] = a;
    __syncthreads();
    for (int off = 128; off > 0; off >>= 1) {
        if (tid < off) red[tid] += red[tid + off];
        __syncthreads();
    }
    float m = red[0] * (1.f / D);
    __syncthreads();
    float c = a - m;
    red[tid] = c * c;
    __syncthreads();
    for (int off = 128; off > 0; off >>= 1) {
        if (tid < off) red[tid] += red[tid + off];
        __syncthreads();
    }
    float sd = sqrtf(red[0] / (float)(D - 1));
    out[2 * N + tid] = c / (sd + 1e-6f);
}

// ---------------------------------------------------------------------------
extern "C" void kernel_launch(void* const* d_in, const int* in_sizes, int n_in,
                              void* d_out, int out_size) {
    const float* E    = (const float*)d_in[0];
    const float* Dx   = (const float*)d_in[1];
    const float* Dy   = (const float*)d_in[2];
    const float* temb = (const float*)d_in[3];
    const int*   toks = (const int*)d_in[4];
    float* out = (float*)d_out;

    const int SM1 = 73728;   // 4 x [128][36w] tiles; epilogue Xs+sx+tot fits
    const int SM2 = 208896;  // cV hi/lo [256][68w] + XT hi/lo [128][68w]
    static int inited = 0;
    static cudaStream_t s2;
    static cudaEvent_t evG, ev1, ev2;
    if (!inited) {
        cudaFuncSetAttribute(k_gemm1, cudaFuncAttributeMaxDynamicSharedMemorySize, SM1);
        cudaFuncSetAttribute(k_gemm2, cudaFuncAttributeMaxDynamicSharedMemorySize, SM2);
        cudaStreamCreateWithFlags(&s2, cudaStreamNonBlocking);
        cudaEventCreateWithFlags(&evG, cudaEventDisableTiming);
        cudaEventCreateWithFlags(&ev1, cudaEventDisableTiming);
        cudaEventCreateWithFlags(&ev2, cudaEventDisableTiming);
        inited = 1;
    }

    k_gather_prep<<<T, 256>>>(temb, toks);
    cudaEventRecord(evG, 0);
    cudaStreamWaitEvent(s2, evG, 0);
    k_prep_cv<<<D, 64, 0, s2>>>();  // overlaps with gemm1

    k_gemm1<<<N / 128, 512, SM1>>>(Dx, out);

    // fork: gemm2 (rho) runs concurrently with the astar->y->u->vstar chain
    cudaEventRecord(ev1, 0);
    cudaStreamWaitEvent(s2, ev1, 0);
    k_gemm2<<<N / 128, 512, SM2, s2>>>(out);
    cudaEventRecord(ev2, s2);

    k_astar_ln<<<1, D>>>();
    k_y<<<N / 8, 256>>>(Dy, out);
    k_u<<<D, 256>>>(E, out);
    k_vstar<<<1, D>>>(out);

    cudaStreamWaitEvent(0, ev2, 0);  // join
}

// round 8
// speedup vs baseline: 1.0589x; 1.0589x over previous
#include <cuda_runtime.h>
#include <cuda_fp16.h>
#include <math.h>

#define N 16384
#define D 256
#define T 128

typedef unsigned int u32;
typedef unsigned long long u64;

// ---------------- scratch ---------------------------------------------------
__device__ float  g_V[T * D];      // gathered token embeddings fp32 [t][d]
__device__ __half g_Vh[T * D];     // V hi fp16 [t][k]
__device__ __half g_Vl[T * D];     // V lo (residual) fp16 [t][k]
__device__ u32    g_XTh[N * 64];   // X^T hi fp16x2 [n][t/2]
__device__ u32    g_XTl[N * 64];   // X^T lo fp16x2
__device__ __half g_cV[D * T];     // (0.97^(T-s)*V[s][d]) single fp16 [d][s]
__device__ float  g_part2[128 * T];
__device__ float  g_lnA[D];
__device__ float  g_u[D];

// ---------------- helpers ----------------------------------------------------
__device__ __forceinline__ u32 s2u(const void* p) {
    u32 a;
    asm("{ .reg .u64 t; cvta.to.shared.u64 t, %1; cvt.u32.u64 %0, t; }" : "=r"(a) : "l"(p));
    return a;
}

#define LDSM_X4(r, addr)                                                        \
    asm volatile(                                                               \
        "ldmatrix.sync.aligned.m8n8.x4.shared.b16 {%0,%1,%2,%3}, [%4];"         \
        : "=r"((r)[0]), "=r"((r)[1]), "=r"((r)[2]), "=r"((r)[3])                \
        : "r"(addr))

__device__ __forceinline__ void mma16816(float* c, const u32* a, u32 b0, u32 b1) {
    asm volatile(
        "mma.sync.aligned.m16n8k16.row.col.f32.f16.f16.f32 "
        "{%0,%1,%2,%3}, {%4,%5,%6,%7}, {%8,%9}, {%0,%1,%2,%3};"
        : "+f"(c[0]), "+f"(c[1]), "+f"(c[2]), "+f"(c[3])
        : "r"(a[0]), "r"(a[1]), "r"(a[2]), "r"(a[3]), "r"(b0), "r"(b1));
}

// float4 -> 4 packed fp16 (u64)
__device__ __forceinline__ u64 to_h4(float4 v) {
    __half2 a = __floats2half2_rn(v.x, v.y);
    __half2 b = __floats2half2_rn(v.z, v.w);
    u32 ua = *(u32*)&a, ub = *(u32*)&b;
    return ((u64)ub << 32) | ua;
}

// ---------------- K1: gather + V splits + cV (fused prep) --------------------
__global__ __launch_bounds__(256) void k_prep(const float* __restrict__ temb,
                                              const int* __restrict__ toks) {
    int t = blockIdx.x, d = threadIdx.x;
    float v = temb[(size_t)toks[t] * D + d];
    g_V[t * D + d] = v;
    __half hv = __float2half_rn(v);
    g_Vh[t * D + d] = hv;
    g_Vl[t * D + d] = __float2half_rn(v - __half2float(hv));
    float c = (float)pow(0.97, (double)(T - t));
    g_cV[d * T + t] = __float2half_rn(c * v);
}

// ---------------- K2: GEMM1 (fp16 2-pass, 512 thr, 32x32 warp tiles) ---------
// C[n][t] = sum_k Dx[n][k]*V[t][k]; epilogue: relu+cumsum, XT splits, partials.
#define PA1 36
__global__ __launch_bounds__(512) void k_gemm1(const float* __restrict__ Dx,
                                               float* __restrict__ out) {
    extern __shared__ char sm[];
    const int S_A = 0, S_BH = 18432, S_BL = 36864;
    int tid = threadIdx.x;
    int lane = tid & 31, wid = tid >> 5;  // 16 warps
    int gr = lane >> 2, gc = lane & 3;
    int r8 = lane & 7, sub = lane >> 3;
    int m0w = (wid & 3) * 32;   // n rows
    int t0 = (wid >> 2) * 32;   // t cols
    int n0 = blockIdx.x * 128;
    u32 smb = s2u(sm);

    float acc[2][4][4];
#pragma unroll
    for (int i = 0; i < 2; i++)
#pragma unroll
        for (int j = 0; j < 4; j++)
#pragma unroll
            for (int q = 0; q < 4; q++) acc[i][j][q] = 0.f;

    float4 pa[4];
#pragma unroll
    for (int r = 0; r < 4; r++) {
        int gi = tid + 512 * r;
        int row = gi >> 4, f4 = gi & 15;
        pa[r] = *(const float4*)&Dx[(size_t)(n0 + row) * D + f4 * 4];
    }

    for (int c = 0; c < 4; c++) {  // K chunks of 64
#pragma unroll
        for (int r = 0; r < 4; r++) {
            int gi = tid + 512 * r;
            int row = gi >> 4, f4 = gi & 15;
            *(u64*)(sm + S_A + row * (PA1 * 4) + f4 * 8) = to_h4(pa[r]);
        }
#pragma unroll
        for (int r = 0; r < 2; r++) {
            int gi = tid + 512 * r;  // 1024 uint4 per split
            int row = gi >> 3, j4 = gi & 7;
            *(uint4*)(sm + S_BH + row * (PA1 * 4) + j4 * 16) =
                ((const uint4*)g_Vh)[row * 32 + c * 8 + j4];
            *(uint4*)(sm + S_BL + row * (PA1 * 4) + j4 * 16) =
                ((const uint4*)g_Vl)[row * 32 + c * 8 + j4];
        }
        __syncthreads();
        if (c < 3) {
#pragma unroll
            for (int r = 0; r < 4; r++) {
                int gi = tid + 512 * r;
                int row = gi >> 4, f4 = gi & 15;
                pa[r] = *(const float4*)&Dx[(size_t)(n0 + row) * D + (c + 1) * 64 + f4 * 4];
            }
        }
#pragma unroll
        for (int ks = 0; ks < 4; ks++) {
            u32 ah[2][4], bh[2][4], bl[2][4];
#pragma unroll
            for (int mt = 0; mt < 2; mt++) {
                int aw = (m0w + mt * 16 + r8 + (sub & 1) * 8) * PA1 + (sub >> 1) * 4 + ks * 8;
                LDSM_X4(ah[mt], smb + S_A + aw * 4);
            }
#pragma unroll
            for (int g = 0; g < 2; g++) {
                int bw = (t0 + g * 16 + r8 + (sub >> 1) * 8) * PA1 + (sub & 1) * 4 + ks * 8;
                LDSM_X4(bh[g], smb + S_BH + bw * 4);
                LDSM_X4(bl[g], smb + S_BL + bw * 4);
            }
            // pass 1: a*bh (8 MMAs, distinct accs)
#pragma unroll
            for (int g = 0; g < 2; g++)
#pragma unroll
                for (int mt = 0; mt < 2; mt++) {
                    mma16816(acc[mt][2 * g], ah[mt], bh[g][0], bh[g][1]);
                    mma16816(acc[mt][2 * g + 1], ah[mt], bh[g][2], bh[g][3]);
                }
            // pass 2: a*bl
#pragma unroll
            for (int g = 0; g < 2; g++)
#pragma unroll
                for (int mt = 0; mt < 2; mt++) {
                    mma16816(acc[mt][2 * g], ah[mt], bl[g][0], bl[g][1]);
                    mma16816(acc[mt][2 * g + 1], ah[mt], bl[g][2], bl[g][3]);
                }
        }
        __syncthreads();
    }

    // ---- epilogue: relu -> Xs[128][130], 4-segment cumsum, splits, partials --
    float* Xs = (float*)sm;
    float* sx = (float*)(sm + 66560);   // [128] x_f
    float* tot = (float*)(sm + 67072);  // [128][4] segment totals
#pragma unroll
    for (int mt = 0; mt < 2; mt++)
#pragma unroll
        for (int j = 0; j < 4; j++) {
            int row = m0w + mt * 16 + gr;
            int col = t0 + j * 8 + 2 * gc;
            *(float2*)&Xs[row * 130 + col] =
                make_float2(fmaxf(acc[mt][j][0], 0.f), fmaxf(acc[mt][j][1], 0.f));
            *(float2*)&Xs[(row + 8) * 130 + col] =
                make_float2(fmaxf(acc[mt][j][2], 0.f), fmaxf(acc[mt][j][3], 0.f));
        }
    __syncthreads();
    {
        int n = tid & 127, q = tid >> 7;  // 4 t-segments of 32
        float v[32];
        float a = 0.f;
#pragma unroll
        for (int i = 0; i < 16; i++) {
            float2 p = *(float2*)&Xs[n * 130 + q * 32 + 2 * i];
            a += p.x;
            v[2 * i] = a;
            a += p.y;
            v[2 * i + 1] = a;
        }
        tot[n * 4 + q] = a;
        __syncthreads();
        float off = 0.f;
#pragma unroll
        for (int qq = 0; qq < 3; qq++)
            if (qq < q) off += tot[n * 4 + qq];
#pragma unroll
        for (int p = 0; p < 16; p++) {
            float x0 = v[2 * p] + off, x1 = v[2 * p + 1] + off;
            *(float2*)&Xs[n * 130 + q * 32 + 2 * p] = make_float2(x0, x1);
            __half2 hp = __floats2half2_rn(x0, x1);
            float r0 = x0 - __half2float(__low2half(hp));
            float r1 = x1 - __half2float(__high2half(hp));
            __half2 lp = __floats2half2_rn(r0, r1);
            g_XTh[(size_t)(n0 + n) * 64 + q * 16 + p] = *(u32*)&hp;
            g_XTl[(size_t)(n0 + n) * 64 + q * 16 + p] = *(u32*)&lp;
        }
        if (q == 3) {
            float xf = v[31] + off;
            out[n0 + n] = xf;
            sx[n] = xf;
        }
    }
    __syncthreads();
    {
        int t = tid & 127, q = tid >> 7;  // 4 n-segments of 32
        float s = 0.f;
#pragma unroll 8
        for (int n2 = q * 32; n2 < q * 32 + 32; n2++)
            s = fmaf(Xs[n2 * 130 + t], sx[n2], s);
        tot[t * 4 + q] = s;
    }
    __syncthreads();
    if (tid < 128)
        g_part2[blockIdx.x * 128 + tid] =
            (tot[tid * 4] + tot[tid * 4 + 1]) + (tot[tid * 4 + 2] + tot[tid * 4 + 3]);
}

// ---------------- K3: GEMM2 (fp16 2-pass, 32x64 warp tiles) ------------------
// C[d][n] = sum_s cV[d][s]*XT[n][s]; coalesced float2 stores to rho[d][n].
#define PA2 68
__global__ __launch_bounds__(512) void k_gemm2(float* __restrict__ out) {
    extern __shared__ char sm[];
    const int S_A = 0, S_BH = 69632, S_BL = 104448;
    int tid = threadIdx.x;
    int lane = tid & 31, wid = tid >> 5;  // 16 warps
    int gr = lane >> 2, gc = lane & 3;
    int r8 = lane & 7, sub = lane >> 3;
    int m0w = (wid & 7) * 32;   // d rows
    int nb = (wid >> 3) * 64;   // n cols within tile
    int n0 = blockIdx.x * 128;
    u32 smb = s2u(sm);

#pragma unroll
    for (int r = 0; r < 8; r++) {
        int gi = tid + 512 * r;  // 4096 uint4
        int row = gi >> 4, j4 = gi & 15;
        *(uint4*)(sm + S_A + row * (PA2 * 4) + j4 * 16) = ((const uint4*)g_cV)[row * 16 + j4];
    }
#pragma unroll
    for (int r = 0; r < 4; r++) {
        int gi = tid + 512 * r;  // 2048 uint4
        int row = gi >> 4, j4 = gi & 15;
        *(uint4*)(sm + S_BH + row * (PA2 * 4) + j4 * 16) =
            ((const uint4*)g_XTh)[(size_t)(n0 + row) * 16 + j4];
        *(uint4*)(sm + S_BL + row * (PA2 * 4) + j4 * 16) =
            ((const uint4*)g_XTl)[(size_t)(n0 + row) * 16 + j4];
    }
    __syncthreads();

    float acc[2][8][4];
#pragma unroll
    for (int i = 0; i < 2; i++)
#pragma unroll
        for (int j = 0; j < 8; j++)
#pragma unroll
            for (int q = 0; q < 4; q++) acc[i][j][q] = 0.f;

#pragma unroll
    for (int ks = 0; ks < 8; ks++) {
        u32 ah[2][4];
#pragma unroll
        for (int mt = 0; mt < 2; mt++) {
            int aw = (m0w + mt * 16 + r8 + (sub & 1) * 8) * PA2 + (sub >> 1) * 4 + ks * 8;
            LDSM_X4(ah[mt], smb + S_A + aw * 4);
        }
#pragma unroll
        for (int g = 0; g < 4; g++) {
            u32 bh[4], bl[4];
            int bw = (nb + g * 16 + r8 + (sub >> 1) * 8) * PA2 + (sub & 1) * 4 + ks * 8;
            LDSM_X4(bh, smb + S_BH + bw * 4);
            LDSM_X4(bl, smb + S_BL + bw * 4);
            mma16816(acc[0][2 * g], ah[0], bh[0], bh[1]);
            mma16816(acc[1][2 * g], ah[1], bh[0], bh[1]);
            mma16816(acc[0][2 * g + 1], ah[0], bh[2], bh[3]);
            mma16816(acc[1][2 * g + 1], ah[1], bh[2], bh[3]);
            mma16816(acc[0][2 * g], ah[0], bl[0], bl[1]);
            mma16816(acc[1][2 * g], ah[1], bl[0], bl[1]);
            mma16816(acc[0][2 * g + 1], ah[0], bl[2], bl[3]);
            mma16816(acc[1][2 * g + 1], ah[1], bl[2], bl[3]);
        }
    }

    float* rho = out + 2 * N + D;
#pragma unroll
    for (int mt = 0; mt < 2; mt++)
#pragma unroll
        for (int j = 0; j < 8; j++) {
            int d = m0w + mt * 16 + gr;
            int col = n0 + nb + j * 8 + 2 * gc;
            *(float2*)&rho[(size_t)d * N + col] = make_float2(acc[mt][j][0], acc[mt][j][1]);
            *(float2*)&rho[(size_t)(d + 8) * N + col] = make_float2(acc[mt][j][2], acc[mt][j][3]);
        }
}

// ---------------- K4: a*[d] -> layernorm -> g_lnA ----------------------------
__global__ void k_astar_ln() {
    __shared__ float gg[T];
    __shared__ float red[256];
    int tid = threadIdx.x;  // = d
    if (tid < T) {
        float s = 0.f;
        for (int b = 0; b < 128; b++) s += g_part2[b * 128 + tid];
        gg[tid] = (tid < T - 1) ? (float)pow(0.97, (double)(T - 1 - tid)) * s : 0.f;
    }
    __syncthreads();
    float a = 0.f;
    for (int s = 0; s < T - 1; s++) a = fmaf(gg[s], g_V[s * D + tid], a);
    red[tid] = a;
    __syncthreads();
    for (int off = 128; off > 0; off >>= 1) {
        if (tid < off) red[tid] += red[tid + off];
        __syncthreads();
    }
    float m = red[0] * (1.f / D);
    __syncthreads();
    float ctr = a - m;
    red[tid] = ctr * ctr;
    __syncthreads();
    for (int off = 128; off > 0; off >>= 1) {
        if (tid < off) red[tid] += red[tid + off];
        __syncthreads();
    }
    float sd = sqrtf(red[0] / (float)(D - 1));
    g_lnA[tid] = ctr / (sd + 1e-6f);
}

// ---------------- K5: y[n] = relu(Dy.lnA) * relu(x_f) -> out[N:2N) ----------
__global__ void k_y(const float* __restrict__ Dy, float* __restrict__ out) {
    __shared__ float sa[D];
    int tid = threadIdx.x;
    sa[tid] = g_lnA[tid];
    __syncthreads();
    int warp = tid >> 5, lane = tid & 31;
    int n = blockIdx.x * 8 + warp;
    const float4* row = (const float4*)&Dy[(size_t)n * D];
    float s = 0.f;
#pragma unroll
    for (int r = 0; r < 2; r++) {
        float4 v = row[lane + 32 * r];
        int d = 4 * (lane + 32 * r);
        s = fmaf(v.x, sa[d], s);
        s = fmaf(v.y, sa[d + 1], s);
        s = fmaf(v.z, sa[d + 2], s);
        s = fmaf(v.w, sa[d + 3], s);
    }
#pragma unroll
    for (int off = 16; off > 0; off >>= 1) s += __shfl_down_sync(0xffffffffu, s, off);
    if (lane == 0) out[N + n] = fmaxf(s, 0.f) * fmaxf(out[n], 0.f);
}

// ---------------- K6: u[d] = E[d,:].y ---------------------------------------
__global__ void k_u(const float* __restrict__ E, const float* __restrict__ out) {
    __shared__ float red[256];
    int d = blockIdx.x, tid = threadIdx.x;
    const float4* e = (const float4*)&E[(size_t)d * N];
    const float4* y = (const float4*)&out[N];
    float s = 0.f;
#pragma unroll 4
    for (int r = 0; r < 16; r++) {
        float4 a = e[tid + 256 * r];
        float4 b = y[tid + 256 * r];
        s = fmaf(a.x, b.x, s);
        s = fmaf(a.y, b.y, s);
        s = fmaf(a.z, b.z, s);
        s = fmaf(a.w, b.w, s);
    }
    red[tid] = s;
    __syncthreads();
    for (int off = 128; off > 0; off >>= 1) {
        if (tid < off) red[tid] += red[tid + off];
        __syncthreads();
    }
    if (tid == 0) g_u[d] = red[0];
}

// ---------------- K7: v* = layernorm(u) -> out[2N:2N+D) ---------------------
__global__ void k_vstar(float* __restrict__ out) {
    __shared__ float red[256];
    int tid = threadIdx.x;
    float a = g_u[tid];
    red[tid] = a;
    __syncthreads();
    for (int off = 128; off > 0; off >>= 1) {
        if (tid < off) red[tid] += red[tid + off];
        __syncthreads();
    }
    float m = red[0] * (1.f / D);
    __syncthreads();
    float c = a - m;
    red[tid] = c * c;
    __syncthreads();
    for (int off = 128; off > 0; off >>= 1) {
        if (tid < off) red[tid] += red[tid + off];
        __syncthreads();
    }
    float sd = sqrtf(red[0] / (float)(D - 1));
    out[2 * N + tid] = c / (sd + 1e-6f);
}

// ---------------------------------------------------------------------------
extern "C" void kernel_launch(void* const* d_in, const int* in_sizes, int n_in,
                              void* d_out, int out_size) {
    const float* E    = (const float*)d_in[0];
    const float* Dx   = (const float*)d_in[1];
    const float* Dy   = (const float*)d_in[2];
    const float* temb = (const float*)d_in[3];
    const int*   toks = (const int*)d_in[4];
    float* out = (float*)d_out;

    const int SM1 = 69632;   // max(tiles 55296, epilogue 69120)
    const int SM2 = 139264;  // cV single + XT hi/lo
    static int inited = 0;
    static cudaStream_t s2;
    static cudaEvent_t ev1, ev2;
    if (!inited) {
        cudaFuncSetAttribute(k_gemm1, cudaFuncAttributeMaxDynamicSharedMemorySize, SM1);
        cudaFuncSetAttribute(k_gemm2, cudaFuncAttributeMaxDynamicSharedMemorySize, SM2);
        cudaStreamCreateWithFlags(&s2, cudaStreamNonBlocking);
        cudaEventCreateWithFlags(&ev1, cudaEventDisableTiming);
        cudaEventCreateWithFlags(&ev2, cudaEventDisableTiming);
        inited = 1;
    }

    k_prep<<<T, 256>>>(temb, toks);
    k_gemm1<<<N / 128, 512, SM1>>>(Dx, out);

    // fork: gemm2 (rho) runs concurrently with the astar->y->u->vstar chain
    cudaEventRecord(ev1, 0);
    cudaStreamWaitEvent(s2, ev1, 0);
    k_gemm2<<<N / 128, 512, SM2, s2>>>(out);
    cudaEventRecord(ev2, s2);

    k_astar_ln<<<1, D>>>();
    k_y<<<N / 8, 256>>>(Dy, out);
    k_u<<<D, 256>>>(E, out);
    k_vstar<<<1, D>>>(out);

    cudaStreamWaitEvent(0, ev2, 0);  // join
}

// round 9
// speedup vs baseline: 1.2690x; 1.1985x over previous
#include <cuda_runtime.h>
#include <cuda_fp16.h>
#include <math.h>

#define N 16384
#define D 256
#define T 128
#define LOG2_097 (-0.04394334758759706f)

typedef unsigned int u32;
typedef unsigned long long u64;

// ---------------- scratch ---------------------------------------------------
__device__ float  g_V[T * D];      // gathered token embeddings fp32 [t][d]
__device__ __half g_Vh[T * D];     // V hi fp16 [t][k]
__device__ __half g_Vl[T * D];     // V lo (residual) fp16 [t][k]
__device__ u32    g_XTh[N * 64];   // X^T hi fp16x2 [n][t/2]
__device__ u32    g_XTl[N * 64];   // X^T lo fp16x2
__device__ __half g_cV[D * T];     // (0.97^(T-s)*V[s][d]) single fp16 [d][s]
__device__ float  g_part2[128 * T];
__device__ float  g_lnA[D];
__device__ float  g_u[D];

// ---------------- helpers ----------------------------------------------------
__device__ __forceinline__ u32 s2u(const void* p) {
    u32 a;
    asm("{ .reg .u64 t; cvta.to.shared.u64 t, %1; cvt.u32.u64 %0, t; }" : "=r"(a) : "l"(p));
    return a;
}

#define LDSM_X4(r, addr)                                                        \
    asm volatile(                                                               \
        "ldmatrix.sync.aligned.m8n8.x4.shared.b16 {%0,%1,%2,%3}, [%4];"         \
        : "=r"((r)[0]), "=r"((r)[1]), "=r"((r)[2]), "=r"((r)[3])                \
        : "r"(addr))

__device__ __forceinline__ void mma16816(float* c, const u32* a, u32 b0, u32 b1) {
    asm volatile(
        "mma.sync.aligned.m16n8k16.row.col.f32.f16.f16.f32 "
        "{%0,%1,%2,%3}, {%4,%5,%6,%7}, {%8,%9}, {%0,%1,%2,%3};"
        : "+f"(c[0]), "+f"(c[1]), "+f"(c[2]), "+f"(c[3])
        : "r"(a[0]), "r"(a[1]), "r"(a[2]), "r"(a[3]), "r"(b0), "r"(b1));
}

// float4 -> 4 packed fp16 (u64)
__device__ __forceinline__ u64 to_h4(float4 v) {
    __half2 a = __floats2half2_rn(v.x, v.y);
    __half2 b = __floats2half2_rn(v.z, v.w);
    u32 ua = *(u32*)&a, ub = *(u32*)&b;
    return ((u64)ub << 32) | ua;
}

// ---------------- K1: gather + V splits + cV (fused prep) --------------------
__global__ __launch_bounds__(256) void k_prep(const float* __restrict__ temb,
                                              const int* __restrict__ toks) {
    int t = blockIdx.x, d = threadIdx.x;
    float v = temb[(size_t)toks[t] * D + d];
    g_V[t * D + d] = v;
    __half hv = __float2half_rn(v);
    g_Vh[t * D + d] = hv;
    g_Vl[t * D + d] = __float2half_rn(v - __half2float(hv));
    float c = exp2f((float)(T - t) * LOG2_097);
    g_cV[d * T + t] = __float2half_rn(c * v);
}

// ---------------- K2: GEMM1 (fp16 2-pass, 512 thr, 32x32 warp tiles) ---------
// C[n][t] = sum_k Dx[n][k]*V[t][k]; epilogue: relu+cumsum, XT splits, partials.
#define PA1 36
__global__ __launch_bounds__(512) void k_gemm1(const float* __restrict__ Dx,
                                               float* __restrict__ out) {
    extern __shared__ char sm[];
    const int S_A = 0, S_BH = 18432, S_BL = 36864;
    int tid = threadIdx.x;
    int lane = tid & 31, wid = tid >> 5;  // 16 warps
    int gr = lane >> 2, gc = lane & 3;
    int r8 = lane & 7, sub = lane >> 3;
    int m0w = (wid & 3) * 32;   // n rows
    int t0 = (wid >> 2) * 32;   // t cols
    int n0 = blockIdx.x * 128;
    u32 smb = s2u(sm);

    float acc[2][4][4];
#pragma unroll
    for (int i = 0; i < 2; i++)
#pragma unroll
        for (int j = 0; j < 4; j++)
#pragma unroll
            for (int q = 0; q < 4; q++) acc[i][j][q] = 0.f;

    float4 pa[4];
#pragma unroll
    for (int r = 0; r < 4; r++) {
        int gi = tid + 512 * r;
        int row = gi >> 4, f4 = gi & 15;
        pa[r] = *(const float4*)&Dx[(size_t)(n0 + row) * D + f4 * 4];
    }

    for (int c = 0; c < 4; c++) {  // K chunks of 64
#pragma unroll
        for (int r = 0; r < 4; r++) {
            int gi = tid + 512 * r;
            int row = gi >> 4, f4 = gi & 15;
            *(u64*)(sm + S_A + row * (PA1 * 4) + f4 * 8) = to_h4(pa[r]);
        }
#pragma unroll
        for (int r = 0; r < 2; r++) {
            int gi = tid + 512 * r;  // 1024 uint4 per split
            int row = gi >> 3, j4 = gi & 7;
            *(uint4*)(sm + S_BH + row * (PA1 * 4) + j4 * 16) =
                ((const uint4*)g_Vh)[row * 32 + c * 8 + j4];
            *(uint4*)(sm + S_BL + row * (PA1 * 4) + j4 * 16) =
                ((const uint4*)g_Vl)[row * 32 + c * 8 + j4];
        }
        __syncthreads();
        if (c < 3) {
#pragma unroll
            for (int r = 0; r < 4; r++) {
                int gi = tid + 512 * r;
                int row = gi >> 4, f4 = gi & 15;
                pa[r] = *(const float4*)&Dx[(size_t)(n0 + row) * D + (c + 1) * 64 + f4 * 4];
            }
        }
#pragma unroll
        for (int ks = 0; ks < 4; ks++) {
            u32 ah[2][4], bh[2][4], bl[2][4];
#pragma unroll
            for (int mt = 0; mt < 2; mt++) {
                int aw = (m0w + mt * 16 + r8 + (sub & 1) * 8) * PA1 + (sub >> 1) * 4 + ks * 8;
                LDSM_X4(ah[mt], smb + S_A + aw * 4);
            }
#pragma unroll
            for (int g = 0; g < 2; g++) {
                int bw = (t0 + g * 16 + r8 + (sub >> 1) * 8) * PA1 + (sub & 1) * 4 + ks * 8;
                LDSM_X4(bh[g], smb + S_BH + bw * 4);
                LDSM_X4(bl[g], smb + S_BL + bw * 4);
            }
#pragma unroll
            for (int g = 0; g < 2; g++)
#pragma unroll
                for (int mt = 0; mt < 2; mt++) {
                    mma16816(acc[mt][2 * g], ah[mt], bh[g][0], bh[g][1]);
                    mma16816(acc[mt][2 * g + 1], ah[mt], bh[g][2], bh[g][3]);
                }
#pragma unroll
            for (int g = 0; g < 2; g++)
#pragma unroll
                for (int mt = 0; mt < 2; mt++) {
                    mma16816(acc[mt][2 * g], ah[mt], bl[g][0], bl[g][1]);
                    mma16816(acc[mt][2 * g + 1], ah[mt], bl[g][2], bl[g][3]);
                }
        }
        __syncthreads();
    }

    // ---- epilogue: relu -> Xs[128][130], 4-segment cumsum, splits, partials --
    float* Xs = (float*)sm;
    float* sx = (float*)(sm + 66560);   // [128] x_f
    float* tot = (float*)(sm + 67072);  // [128][4] segment totals
#pragma unroll
    for (int mt = 0; mt < 2; mt++)
#pragma unroll
        for (int j = 0; j < 4; j++) {
            int row = m0w + mt * 16 + gr;
            int col = t0 + j * 8 + 2 * gc;
            *(float2*)&Xs[row * 130 + col] =
                make_float2(fmaxf(acc[mt][j][0], 0.f), fmaxf(acc[mt][j][1], 0.f));
            *(float2*)&Xs[(row + 8) * 130 + col] =
                make_float2(fmaxf(acc[mt][j][2], 0.f), fmaxf(acc[mt][j][3], 0.f));
        }
    __syncthreads();
    {
        int n = tid & 127, q = tid >> 7;  // 4 t-segments of 32
        float v[32];
        float a = 0.f;
#pragma unroll
        for (int i = 0; i < 16; i++) {
            float2 p = *(float2*)&Xs[n * 130 + q * 32 + 2 * i];
            a += p.x;
            v[2 * i] = a;
            a += p.y;
            v[2 * i + 1] = a;
        }
        tot[n * 4 + q] = a;
        __syncthreads();
        float off = 0.f;
#pragma unroll
        for (int qq = 0; qq < 3; qq++)
            if (qq < q) off += tot[n * 4 + qq];
#pragma unroll
        for (int p = 0; p < 16; p++) {
            float x0 = v[2 * p] + off, x1 = v[2 * p + 1] + off;
            *(float2*)&Xs[n * 130 + q * 32 + 2 * p] = make_float2(x0, x1);
            __half2 hp = __floats2half2_rn(x0, x1);
            float r0 = x0 - __half2float(__low2half(hp));
            float r1 = x1 - __half2float(__high2half(hp));
            __half2 lp = __floats2half2_rn(r0, r1);
            g_XTh[(size_t)(n0 + n) * 64 + q * 16 + p] = *(u32*)&hp;
            g_XTl[(size_t)(n0 + n) * 64 + q * 16 + p] = *(u32*)&lp;
        }
        if (q == 3) {
            float xf = v[31] + off;
            out[n0 + n] = xf;
            sx[n] = xf;
        }
    }
    __syncthreads();
    {
        int t = tid & 127, q = tid >> 7;  // 4 n-segments of 32
        float s = 0.f;
#pragma unroll 8
        for (int n2 = q * 32; n2 < q * 32 + 32; n2++)
            s = fmaf(Xs[n2 * 130 + t], sx[n2], s);
        tot[t * 4 + q] = s;
    }
    __syncthreads();
    if (tid < 128)
        g_part2[blockIdx.x * 128 + tid] =
            (tot[tid * 4] + tot[tid * 4 + 1]) + (tot[tid * 4 + 2] + tot[tid * 4 + 3]);
}

// ---------------- K3: GEMM2 (fp16 2-pass, 32x64 warp tiles) ------------------
// C[d][n] = sum_s cV[d][s]*XT[n][s]; coalesced float2 stores to rho[d][n].
#define PA2 68
__global__ __launch_bounds__(512) void k_gemm2(float* __restrict__ out) {
    extern __shared__ char sm[];
    const int S_A = 0, S_BH = 69632, S_BL = 104448;
    int tid = threadIdx.x;
    int lane = tid & 31, wid = tid >> 5;  // 16 warps
    int gr = lane >> 2, gc = lane & 3;
    int r8 = lane & 7, sub = lane >> 3;
    int m0w = (wid & 7) * 32;   // d rows
    int nb = (wid >> 3) * 64;   // n cols within tile
    int n0 = blockIdx.x * 128;
    u32 smb = s2u(sm);

#pragma unroll
    for (int r = 0; r < 8; r++) {
        int gi = tid + 512 * r;  // 4096 uint4
        int row = gi >> 4, j4 = gi & 15;
        *(uint4*)(sm + S_A + row * (PA2 * 4) + j4 * 16) = ((const uint4*)g_cV)[row * 16 + j4];
    }
#pragma unroll
    for (int r = 0; r < 4; r++) {
        int gi = tid + 512 * r;  // 2048 uint4
        int row = gi >> 4, j4 = gi & 15;
        *(uint4*)(sm + S_BH + row * (PA2 * 4) + j4 * 16) =
            ((const uint4*)g_XTh)[(size_t)(n0 + row) * 16 + j4];
        *(uint4*)(sm + S_BL + row * (PA2 * 4) + j4 * 16) =
            ((const uint4*)g_XTl)[(size_t)(n0 + row) * 16 + j4];
    }
    __syncthreads();

    float acc[2][8][4];
#pragma unroll
    for (int i = 0; i < 2; i++)
#pragma unroll
        for (int j = 0; j < 8; j++)
#pragma unroll
            for (int q = 0; q < 4; q++) acc[i][j][q] = 0.f;

#pragma unroll
    for (int ks = 0; ks < 8; ks++) {
        u32 ah[2][4];
#pragma unroll
        for (int mt = 0; mt < 2; mt++) {
            int aw = (m0w + mt * 16 + r8 + (sub & 1) * 8) * PA2 + (sub >> 1) * 4 + ks * 8;
            LDSM_X4(ah[mt], smb + S_A + aw * 4);
        }
#pragma unroll
        for (int g = 0; g < 4; g++) {
            u32 bh[4], bl[4];
            int bw = (nb + g * 16 + r8 + (sub >> 1) * 8) * PA2 + (sub & 1) * 4 + ks * 8;
            LDSM_X4(bh, smb + S_BH + bw * 4);
            LDSM_X4(bl, smb + S_BL + bw * 4);
            mma16816(acc[0][2 * g], ah[0], bh[0], bh[1]);
            mma16816(acc[1][2 * g], ah[1], bh[0], bh[1]);
            mma16816(acc[0][2 * g + 1], ah[0], bh[2], bh[3]);
            mma16816(acc[1][2 * g + 1], ah[1], bh[2], bh[3]);
            mma16816(acc[0][2 * g], ah[0], bl[0], bl[1]);
            mma16816(acc[1][2 * g], ah[1], bl[0], bl[1]);
            mma16816(acc[0][2 * g + 1], ah[0], bl[2], bl[3]);
            mma16816(acc[1][2 * g + 1], ah[1], bl[2], bl[3]);
        }
    }

    float* rho = out + 2 * N + D;
#pragma unroll
    for (int mt = 0; mt < 2; mt++)
#pragma unroll
        for (int j = 0; j < 8; j++) {
            int d = m0w + mt * 16 + gr;
            int col = n0 + nb + j * 8 + 2 * gc;
            *(float2*)&rho[(size_t)d * N + col] = make_float2(acc[mt][j][0], acc[mt][j][1]);
            *(float2*)&rho[(size_t)(d + 8) * N + col] = make_float2(acc[mt][j][2], acc[mt][j][3]);
        }
}

// ---------------- K4: a*[d] -> layernorm -> g_lnA (no FP64!) -----------------
__global__ __launch_bounds__(256) void k_astar_ln() {
    __shared__ float gg[T];
    __shared__ float red[256];
    int tid = threadIdx.x;
    // phase 1: reduce g_part2 over 128 blocks, 2 threads per t
    {
        int t = tid & 127, h = tid >> 7;
        float s = 0.f;
#pragma unroll 16
        for (int b = h * 64; b < h * 64 + 64; b++) s += g_part2[b * 128 + t];
        red[tid] = s;
    }
    __syncthreads();
    if (tid < T) {
        float s = red[tid] + red[128 + tid];
        float c = exp2f((float)(T - 1 - tid) * LOG2_097);
        gg[tid] = (tid < T - 1) ? c * s : 0.f;
    }
    __syncthreads();
    float a = 0.f;
#pragma unroll 8
    for (int s = 0; s < T - 1; s++) a = fmaf(gg[s], g_V[s * D + tid], a);
    red[tid] = a;
    __syncthreads();
    for (int off = 128; off > 0; off >>= 1) {
        if (tid < off) red[tid] += red[tid + off];
        __syncthreads();
    }
    float m = red[0] * (1.f / D);
    __syncthreads();
    float ctr = a - m;
    red[tid] = ctr * ctr;
    __syncthreads();
    for (int off = 128; off > 0; off >>= 1) {
        if (tid < off) red[tid] += red[tid + off];
        __syncthreads();
    }
    float sd = sqrtf(red[0] / (float)(D - 1));
    g_lnA[tid] = ctr / (sd + 1e-6f);
}

// ---------------- K5: y[n] = relu(Dy.lnA) * relu(x_f) -> out[N:2N) ----------
__global__ void k_y(const float* __restrict__ Dy, float* __restrict__ out) {
    __shared__ float sa[D];
    int tid = threadIdx.x;
    sa[tid] = g_lnA[tid];
    __syncthreads();
    int warp = tid >> 5, lane = tid & 31;
    int n = blockIdx.x * 8 + warp;
    const float4* row = (const float4*)&Dy[(size_t)n * D];
    float s = 0.f;
#pragma unroll
    for (int r = 0; r < 2; r++) {
        float4 v = row[lane + 32 * r];
        int d = 4 * (lane + 32 * r);
        s = fmaf(v.x, sa[d], s);
        s = fmaf(v.y, sa[d + 1], s);
        s = fmaf(v.z, sa[d + 2], s);
        s = fmaf(v.w, sa[d + 3], s);
    }
#pragma unroll
    for (int off = 16; off > 0; off >>= 1) s += __shfl_down_sync(0xffffffffu, s, off);
    if (lane == 0) out[N + n] = fmaxf(s, 0.f) * fmaxf(out[n], 0.f);
}

// ---------------- K6: u[d] = E[d,:].y ---------------------------------------
__global__ void k_u(const float* __restrict__ E, const float* __restrict__ out) {
    __shared__ float red[256];
    int d = blockIdx.x, tid = threadIdx.x;
    const float4* e = (const float4*)&E[(size_t)d * N];
    const float4* y = (const float4*)&out[N];
    float s = 0.f;
#pragma unroll 4
    for (int r = 0; r < 16; r++) {
        float4 a = e[tid + 256 * r];
        float4 b = y[tid + 256 * r];
        s = fmaf(a.x, b.x, s);
        s = fmaf(a.y, b.y, s);
        s = fmaf(a.z, b.z, s);
        s = fmaf(a.w, b.w, s);
    }
    red[tid] = s;
    __syncthreads();
    for (int off = 128; off > 0; off >>= 1) {
        if (tid < off) red[tid] += red[tid + off];
        __syncthreads();
    }
    if (tid == 0) g_u[d] = red[0];
}

// ---------------- K7: v* = layernorm(u) -> out[2N:2N+D) ---------------------
__global__ void k_vstar(float* __restrict__ out) {
    __shared__ float red[256];
    int tid = threadIdx.x;
    float a = g_u[tid];
    red[tid] = a;
    __syncthreads();
    for (int off = 128; off > 0; off >>= 1) {
        if (tid < off) red[tid] += red[tid + off];
        __syncthreads();
    }
    float m = red[0] * (1.f / D);
    __syncthreads();
    float c = a - m;
    red[tid] = c * c;
    __syncthreads();
    for (int off = 128; off > 0; off >>= 1) {
        if (tid < off) red[tid] += red[tid + off];
        __syncthreads();
    }
    float sd = sqrtf(red[0] / (float)(D - 1));
    out[2 * N + tid] = c / (sd + 1e-6f);
}

// ---------------------------------------------------------------------------
extern "C" void kernel_launch(void* const* d_in, const int* in_sizes, int n_in,
                              void* d_out, int out_size) {
    const float* E    = (const float*)d_in[0];
    const float* Dx   = (const float*)d_in[1];
    const float* Dy   = (const float*)d_in[2];
    const float* temb = (const float*)d_in[3];
    const int*   toks = (const int*)d_in[4];
    float* out = (float*)d_out;

    const int SM1 = 69632;   // max(tiles 55296, epilogue 69120)
    const int SM2 = 139264;  // cV single + XT hi/lo
    static int inited = 0;
    static cudaStream_t s2;
    static cudaEvent_t ev1, ev2;
    if (!inited) {
        cudaFuncSetAttribute(k_gemm1, cudaFuncAttributeMaxDynamicSharedMemorySize, SM1);
        cudaFuncSetAttribute(k_gemm2, cudaFuncAttributeMaxDynamicSharedMemorySize, SM2);
        cudaStreamCreateWithFlags(&s2, cudaStreamNonBlocking);
        cudaEventCreateWithFlags(&ev1, cudaEventDisableTiming);
        cudaEventCreateWithFlags(&ev2, cudaEventDisableTiming);
        inited = 1;
    }

    k_prep<<<T, 256>>>(temb, toks);
    k_gemm1<<<N / 128, 512, SM1>>>(Dx, out);

    // fork: gemm2 (rho) runs concurrently with the astar->y->u->vstar chain
    cudaEventRecord(ev1, 0);
    cudaStreamWaitEvent(s2, ev1, 0);
    k_gemm2<<<N / 128, 512, SM2, s2>>>(out);
    cudaEventRecord(ev2, s2);

    k_astar_ln<<<1, D>>>();
    k_y<<<N / 8, 256>>>(Dy, out);
    k_u<<<D, 256>>>(E, out);
    k_vstar<<<1, D>>>(out);

    cudaStreamWaitEvent(0, ev2, 0);  // join
}

// round 10
// speedup vs baseline: 1.2898x; 1.0163x over previous
#include <cuda_runtime.h>
#include <cuda_fp16.h>
#include <math.h>

#define N 16384
#define D 256
#define T 128
#define LOG2_097 (-0.04394334758759706f)

typedef unsigned int u32;
typedef unsigned long long u64;

// ---------------- scratch ---------------------------------------------------
__device__ float  g_V[T * D];      // gathered token embeddings fp32 [t][d]
__device__ __half g_Vh[T * D];     // V hi fp16 [t][k]
__device__ __half g_Vl[T * D];     // V lo (residual) fp16 [t][k]
__device__ u32    g_XTh[N * 64];   // X^T hi fp16x2 [n][t/2]
__device__ u32    g_XTl[N * 64];   // X^T lo fp16x2
__device__ __half g_cV[D * T];     // (0.97^(T-s)*V[s][d]) single fp16 [d][s]
__device__ float  g_part2[128 * T];
__device__ float  g_lnA[D];
__device__ float  g_u[D];

// ---------------- helpers ----------------------------------------------------
__device__ __forceinline__ u32 s2u(const void* p) {
    u32 a;
    asm("{ .reg .u64 t; cvta.to.shared.u64 t, %1; cvt.u32.u64 %0, t; }" : "=r"(a) : "l"(p));
    return a;
}

#define LDSM_X4(r, addr)                                                        \
    asm volatile(                                                               \
        "ldmatrix.sync.aligned.m8n8.x4.shared.b16 {%0,%1,%2,%3}, [%4];"         \
        : "=r"((r)[0]), "=r"((r)[1]), "=r"((r)[2]), "=r"((r)[3])                \
        : "r"(addr))

__device__ __forceinline__ void mma16816(float* c, const u32* a, u32 b0, u32 b1) {
    asm volatile(
        "mma.sync.aligned.m16n8k16.row.col.f32.f16.f16.f32 "
        "{%0,%1,%2,%3}, {%4,%5,%6,%7}, {%8,%9}, {%0,%1,%2,%3};"
        : "+f"(c[0]), "+f"(c[1]), "+f"(c[2]), "+f"(c[3])
        : "r"(a[0]), "r"(a[1]), "r"(a[2]), "r"(a[3]), "r"(b0), "r"(b1));
}

// float4 -> 4 packed fp16 (u64)
__device__ __forceinline__ u64 to_h4(float4 v) {
    __half2 a = __floats2half2_rn(v.x, v.y);
    __half2 b = __floats2half2_rn(v.z, v.w);
    u32 ua = *(u32*)&a, ub = *(u32*)&b;
    return ((u64)ub << 32) | ua;
}

// ---------------- K1: gather + V splits + cV (fused prep) --------------------
__global__ __launch_bounds__(256) void k_prep(const float* __restrict__ temb,
                                              const int* __restrict__ toks) {
    int t = blockIdx.x, d = threadIdx.x;
    float v = temb[(size_t)toks[t] * D + d];
    g_V[t * D + d] = v;
    __half hv = __float2half_rn(v);
    g_Vh[t * D + d] = hv;
    g_Vl[t * D + d] = __float2half_rn(v - __half2float(hv));
    float c = exp2f((float)(T - t) * LOG2_097);
    g_cV[d * T + t] = __float2half_rn(c * v);
}

// ---------------- K2: GEMM1 (fp16 2-pass, 512 thr, 32x32 warp tiles) ---------
// C[n][t] = sum_k Dx[n][k]*V[t][k]; epilogue: relu+cumsum, XT splits, partials.
#define PA1 36
__global__ __launch_bounds__(512) void k_gemm1(const float* __restrict__ Dx,
                                               float* __restrict__ out) {
    extern __shared__ char sm[];
    const int S_A = 0, S_BH = 18432, S_BL = 36864;
    int tid = threadIdx.x;
    int lane = tid & 31, wid = tid >> 5;  // 16 warps
    int gr = lane >> 2, gc = lane & 3;
    int r8 = lane & 7, sub = lane >> 3;
    int m0w = (wid & 3) * 32;   // n rows
    int t0 = (wid >> 2) * 32;   // t cols
    int n0 = blockIdx.x * 128;
    u32 smb = s2u(sm);

    float acc[2][4][4];
#pragma unroll
    for (int i = 0; i < 2; i++)
#pragma unroll
        for (int j = 0; j < 4; j++)
#pragma unroll
            for (int q = 0; q < 4; q++) acc[i][j][q] = 0.f;

    // prefetch chunk 0: A (Dx) and B (Vh/Vl)
    float4 pa[4];
    uint4 pbh[2], pbl[2];
#pragma unroll
    for (int r = 0; r < 4; r++) {
        int gi = tid + 512 * r;
        int row = gi >> 4, f4 = gi & 15;
        pa[r] = *(const float4*)&Dx[(size_t)(n0 + row) * D + f4 * 4];
    }
#pragma unroll
    for (int r = 0; r < 2; r++) {
        int gi = tid + 512 * r;
        int row = gi >> 3, j4 = gi & 7;
        pbh[r] = ((const uint4*)g_Vh)[row * 32 + j4];
        pbl[r] = ((const uint4*)g_Vl)[row * 32 + j4];
    }

    for (int c = 0; c < 4; c++) {  // K chunks of 64
#pragma unroll
        for (int r = 0; r < 4; r++) {
            int gi = tid + 512 * r;
            int row = gi >> 4, f4 = gi & 15;
            *(u64*)(sm + S_A + row * (PA1 * 4) + f4 * 8) = to_h4(pa[r]);
        }
#pragma unroll
        for (int r = 0; r < 2; r++) {
            int gi = tid + 512 * r;
            int row = gi >> 3, j4 = gi & 7;
            *(uint4*)(sm + S_BH + row * (PA1 * 4) + j4 * 16) = pbh[r];
            *(uint4*)(sm + S_BL + row * (PA1 * 4) + j4 * 16) = pbl[r];
        }
        __syncthreads();
        if (c < 3) {
#pragma unroll
            for (int r = 0; r < 4; r++) {
                int gi = tid + 512 * r;
                int row = gi >> 4, f4 = gi & 15;
                pa[r] = *(const float4*)&Dx[(size_t)(n0 + row) * D + (c + 1) * 64 + f4 * 4];
            }
#pragma unroll
            for (int r = 0; r < 2; r++) {
                int gi = tid + 512 * r;
                int row = gi >> 3, j4 = gi & 7;
                pbh[r] = ((const uint4*)g_Vh)[row * 32 + (c + 1) * 8 + j4];
                pbl[r] = ((const uint4*)g_Vl)[row * 32 + (c + 1) * 8 + j4];
            }
        }
#pragma unroll
        for (int ks = 0; ks < 4; ks++) {
            u32 ah[2][4], bh[2][4], bl[2][4];
#pragma unroll
            for (int mt = 0; mt < 2; mt++) {
                int aw = (m0w + mt * 16 + r8 + (sub & 1) * 8) * PA1 + (sub >> 1) * 4 + ks * 8;
                LDSM_X4(ah[mt], smb + S_A + aw * 4);
            }
#pragma unroll
            for (int g = 0; g < 2; g++) {
                int bw = (t0 + g * 16 + r8 + (sub >> 1) * 8) * PA1 + (sub & 1) * 4 + ks * 8;
                LDSM_X4(bh[g], smb + S_BH + bw * 4);
                LDSM_X4(bl[g], smb + S_BL + bw * 4);
            }
#pragma unroll
            for (int g = 0; g < 2; g++)
#pragma unroll
                for (int mt = 0; mt < 2; mt++) {
                    mma16816(acc[mt][2 * g], ah[mt], bh[g][0], bh[g][1]);
                    mma16816(acc[mt][2 * g + 1], ah[mt], bh[g][2], bh[g][3]);
                }
#pragma unroll
            for (int g = 0; g < 2; g++)
#pragma unroll
                for (int mt = 0; mt < 2; mt++) {
                    mma16816(acc[mt][2 * g], ah[mt], bl[g][0], bl[g][1]);
                    mma16816(acc[mt][2 * g + 1], ah[mt], bl[g][2], bl[g][3]);
                }
        }
        __syncthreads();
    }

    // ---- epilogue: relu -> Xs[128][130], 4-segment cumsum, splits, partials --
    float* Xs = (float*)sm;
    float* sx = (float*)(sm + 66560);   // [128] x_f
    float* tot = (float*)(sm + 67072);  // [128][4] segment totals
#pragma unroll
    for (int mt = 0; mt < 2; mt++)
#pragma unroll
        for (int j = 0; j < 4; j++) {
            int row = m0w + mt * 16 + gr;
            int col = t0 + j * 8 + 2 * gc;
            *(float2*)&Xs[row * 130 + col] =
                make_float2(fmaxf(acc[mt][j][0], 0.f), fmaxf(acc[mt][j][1], 0.f));
            *(float2*)&Xs[(row + 8) * 130 + col] =
                make_float2(fmaxf(acc[mt][j][2], 0.f), fmaxf(acc[mt][j][3], 0.f));
        }
    __syncthreads();
    {
        int n = tid & 127, q = tid >> 7;  // 4 t-segments of 32
        float v[32];
        float a = 0.f;
#pragma unroll
        for (int i = 0; i < 16; i++) {
            float2 p = *(float2*)&Xs[n * 130 + q * 32 + 2 * i];
            a += p.x;
            v[2 * i] = a;
            a += p.y;
            v[2 * i + 1] = a;
        }
        tot[n * 4 + q] = a;
        __syncthreads();
        float off = 0.f;
#pragma unroll
        for (int qq = 0; qq < 3; qq++)
            if (qq < q) off += tot[n * 4 + qq];
#pragma unroll
        for (int p = 0; p < 16; p++) {
            float x0 = v[2 * p] + off, x1 = v[2 * p + 1] + off;
            *(float2*)&Xs[n * 130 + q * 32 + 2 * p] = make_float2(x0, x1);
            __half2 hp = __floats2half2_rn(x0, x1);
            float r0 = x0 - __half2float(__low2half(hp));
            float r1 = x1 - __half2float(__high2half(hp));
            __half2 lp = __floats2half2_rn(r0, r1);
            g_XTh[(size_t)(n0 + n) * 64 + q * 16 + p] = *(u32*)&hp;
            g_XTl[(size_t)(n0 + n) * 64 + q * 16 + p] = *(u32*)&lp;
        }
        if (q == 3) {
            float xf = v[31] + off;
            out[n0 + n] = xf;
            sx[n] = xf;
        }
    }
    __syncthreads();
    {
        int t = tid & 127, q = tid >> 7;  // 4 n-segments of 32
        float s = 0.f;
#pragma unroll 8
        for (int n2 = q * 32; n2 < q * 32 + 32; n2++)
            s = fmaf(Xs[n2 * 130 + t], sx[n2], s);
        tot[t * 4 + q] = s;
    }
    __syncthreads();
    if (tid < 128)
        g_part2[blockIdx.x * 128 + tid] =
            (tot[tid * 4] + tot[tid * 4 + 1]) + (tot[tid * 4 + 2] + tot[tid * 4 + 3]);
}

// ---------------- K3: GEMM2 (fp16 2-pass, 32x64 warp tiles) ------------------
// C[d][n] = sum_s cV[d][s]*XT[n][s]; coalesced float2 stores to rho[d][n].
#define PA2 68
__global__ __launch_bounds__(512) void k_gemm2(float* __restrict__ out) {
    extern __shared__ char sm[];
    const int S_A = 0, S_BH = 69632, S_BL = 104448;
    int tid = threadIdx.x;
    int lane = tid & 31, wid = tid >> 5;  // 16 warps
    int gr = lane >> 2, gc = lane & 3;
    int r8 = lane & 7, sub = lane >> 3;
    int m0w = (wid & 7) * 32;   // d rows
    int nb = (wid >> 3) * 64;   // n cols within tile
    int n0 = blockIdx.x * 128;
    u32 smb = s2u(sm);

#pragma unroll
    for (int r = 0; r < 8; r++) {
        int gi = tid + 512 * r;  // 4096 uint4
        int row = gi >> 4, j4 = gi & 15;
        *(uint4*)(sm + S_A + row * (PA2 * 4) + j4 * 16) = ((const uint4*)g_cV)[row * 16 + j4];
    }
#pragma unroll
    for (int r = 0; r < 4; r++) {
        int gi = tid + 512 * r;  // 2048 uint4
        int row = gi >> 4, j4 = gi & 15;
        *(uint4*)(sm + S_BH + row * (PA2 * 4) + j4 * 16) =
            ((const uint4*)g_XTh)[(size_t)(n0 + row) * 16 + j4];
        *(uint4*)(sm + S_BL + row * (PA2 * 4) + j4 * 16) =
            ((const uint4*)g_XTl)[(size_t)(n0 + row) * 16 + j4];
    }
    __syncthreads();

    float acc[2][8][4];
#pragma unroll
    for (int i = 0; i < 2; i++)
#pragma unroll
        for (int j = 0; j < 8; j++)
#pragma unroll
            for (int q = 0; q < 4; q++) acc[i][j][q] = 0.f;

#pragma unroll
    for (int ks = 0; ks < 8; ks++) {
        u32 ah[2][4];
#pragma unroll
        for (int mt = 0; mt < 2; mt++) {
            int aw = (m0w + mt * 16 + r8 + (sub & 1) * 8) * PA2 + (sub >> 1) * 4 + ks * 8;
            LDSM_X4(ah[mt], smb + S_A + aw * 4);
        }
#pragma unroll
        for (int g = 0; g < 4; g++) {
            u32 bh[4], bl[4];
            int bw = (nb + g * 16 + r8 + (sub >> 1) * 8) * PA2 + (sub & 1) * 4 + ks * 8;
            LDSM_X4(bh, smb + S_BH + bw * 4);
            LDSM_X4(bl, smb + S_BL + bw * 4);
            mma16816(acc[0][2 * g], ah[0], bh[0], bh[1]);
            mma16816(acc[1][2 * g], ah[1], bh[0], bh[1]);
            mma16816(acc[0][2 * g + 1], ah[0], bh[2], bh[3]);
            mma16816(acc[1][2 * g + 1], ah[1], bh[2], bh[3]);
            mma16816(acc[0][2 * g], ah[0], bl[0], bl[1]);
            mma16816(acc[1][2 * g], ah[1], bl[0], bl[1]);
            mma16816(acc[0][2 * g + 1], ah[0], bl[2], bl[3]);
            mma16816(acc[1][2 * g + 1], ah[1], bl[2], bl[3]);
        }
    }

    float* rho = out + 2 * N + D;
#pragma unroll
    for (int mt = 0; mt < 2; mt++)
#pragma unroll
        for (int j = 0; j < 8; j++) {
            int d = m0w + mt * 16 + gr;
            int col = n0 + nb + j * 8 + 2 * gc;
            *(float2*)&rho[(size_t)d * N + col] = make_float2(acc[mt][j][0], acc[mt][j][1]);
            *(float2*)&rho[(size_t)(d + 8) * N + col] = make_float2(acc[mt][j][2], acc[mt][j][3]);
        }
}

// ---------------- K4: a*[d] -> layernorm -> g_lnA (1024 thr, high MLP) -------
__global__ __launch_bounds__(1024) void k_astar_ln() {
    __shared__ float p1[1024];   // phase-1 partials [8 q][128 t]
    __shared__ float gg[T];
    __shared__ float p2[1024];   // phase-2 partials [4 q][256 d]
    __shared__ float red[256];
    int tid = threadIdx.x;

    // phase 1: reduce g_part2[128 b][128 t] -- 8 threads per t, 16 loads each
    {
        int t = tid & 127, q = tid >> 7;  // q in [0,8)
        float s = 0.f;
#pragma unroll
        for (int b = q * 16; b < q * 16 + 16; b++) s += g_part2[b * 128 + t];
        p1[q * 128 + t] = s;
    }
    __syncthreads();
    if (tid < T) {
        float s = 0.f;
#pragma unroll
        for (int q = 0; q < 8; q++) s += p1[q * 128 + tid];
        float c = exp2f((float)(T - 1 - tid) * LOG2_097);
        gg[tid] = (tid < T - 1) ? c * s : 0.f;
    }
    __syncthreads();

    // phase 2: a[d] = sum_s gg[s]*V[s][d] -- 4 threads per d, 32 loads each
    {
        int d = tid & 255, q = tid >> 8;  // q in [0,4)
        float a = 0.f;
#pragma unroll
        for (int i = 0; i < 32; i++) {
            int s = q * 32 + i;
            a = fmaf(gg[s], g_V[s * D + d], a);  // gg[127]==0
        }
        p2[q * 256 + d] = a;
    }
    __syncthreads();

    // layernorm over d (first 256 threads compute; all threads sync)
    float a = 0.f;
    if (tid < 256) {
        a = (p2[tid] + p2[256 + tid]) + (p2[512 + tid] + p2[768 + tid]);
        red[tid] = a;
    }
    __syncthreads();
    for (int off = 128; off > 0; off >>= 1) {
        if (tid < off) red[tid] += red[tid + off];
        __syncthreads();
    }
    float m = red[0] * (1.f / D);
    __syncthreads();
    float ctr = a - m;
    if (tid < 256) red[tid] = ctr * ctr;
    __syncthreads();
    for (int off = 128; off > 0; off >>= 1) {
        if (tid < off) red[tid] += red[tid + off];
        __syncthreads();
    }
    if (tid < 256) {
        float sd = sqrtf(red[0] / (float)(D - 1));
        g_lnA[tid] = ctr / (sd + 1e-6f);
    }
}

// ---------------- K5: y[n] = relu(Dy.lnA) * relu(x_f) -> out[N:2N) ----------
__global__ void k_y(const float* __restrict__ Dy, float* __restrict__ out) {
    __shared__ float sa[D];
    int tid = threadIdx.x;
    sa[tid] = g_lnA[tid];
    __syncthreads();
    int warp = tid >> 5, lane = tid & 31;
    int n = blockIdx.x * 8 + warp;
    const float4* row = (const float4*)&Dy[(size_t)n * D];
    float s = 0.f;
#pragma unroll
    for (int r = 0; r < 2; r++) {
        float4 v = row[lane + 32 * r];
        int d = 4 * (lane + 32 * r);
        s = fmaf(v.x, sa[d], s);
        s = fmaf(v.y, sa[d + 1], s);
        s = fmaf(v.z, sa[d + 2], s);
        s = fmaf(v.w, sa[d + 3], s);
    }
#pragma unroll
    for (int off = 16; off > 0; off >>= 1) s += __shfl_down_sync(0xffffffffu, s, off);
    if (lane == 0) out[N + n] = fmaxf(s, 0.f) * fmaxf(out[n], 0.f);
}

// ---------------- K6: u[d] = E[d,:].y ---------------------------------------
__global__ void k_u(const float* __restrict__ E, const float* __restrict__ out) {
    __shared__ float red[256];
    int d = blockIdx.x, tid = threadIdx.x;
    const float4* e = (const float4*)&E[(size_t)d * N];
    const float4* y = (const float4*)&out[N];
    float s = 0.f;
#pragma unroll 4
    for (int r = 0; r < 16; r++) {
        float4 a = e[tid + 256 * r];
        float4 b = y[tid + 256 * r];
        s = fmaf(a.x, b.x, s);
        s = fmaf(a.y, b.y, s);
        s = fmaf(a.z, b.z, s);
        s = fmaf(a.w, b.w, s);
    }
    red[tid] = s;
    __syncthreads();
    for (int off = 128; off > 0; off >>= 1) {
        if (tid < off) red[tid] += red[tid + off];
        __syncthreads();
    }
    if (tid == 0) g_u[d] = red[0];
}

// ---------------- K7: v* = layernorm(u) -> out[2N:2N+D) ---------------------
__global__ void k_vstar(float* __restrict__ out) {
    __shared__ float red[256];
    int tid = threadIdx.x;
    float a = g_u[tid];
    red[tid] = a;
    __syncthreads();
    for (int off = 128; off > 0; off >>= 1) {
        if (tid < off) red[tid] += red[tid + off];
        __syncthreads();
    }
    float m = red[0] * (1.f / D);
    __syncthreads();
    float c = a - m;
    red[tid] = c * c;
    __syncthreads();
    for (int off = 128; off > 0; off >>= 1) {
        if (tid < off) red[tid] += red[tid + off];
        __syncthreads();
    }
    float sd = sqrtf(red[0] / (float)(D - 1));
    out[2 * N + tid] = c / (sd + 1e-6f);
}

// ---------------------------------------------------------------------------
extern "C" void kernel_launch(void* const* d_in, const int* in_sizes, int n_in,
                              void* d_out, int out_size) {
    const float* E    = (const float*)d_in[0];
    const float* Dx   = (const float*)d_in[1];
    const float* Dy   = (const float*)d_in[2];
    const float* temb = (const float*)d_in[3];
    const int*   toks = (const int*)d_in[4];
    float* out = (float*)d_out;

    const int SM1 = 69632;   // max(tiles 55296, epilogue 69120)
    const int SM2 = 139264;  // cV single + XT hi/lo
    static int inited = 0;
    static cudaStream_t s2;
    static cudaEvent_t ev1, ev2;
    if (!inited) {
        cudaFuncSetAttribute(k_gemm1, cudaFuncAttributeMaxDynamicSharedMemorySize, SM1);
        cudaFuncSetAttribute(k_gemm2, cudaFuncAttributeMaxDynamicSharedMemorySize, SM2);
        cudaStreamCreateWithFlags(&s2, cudaStreamNonBlocking);
        cudaEventCreateWithFlags(&ev1, cudaEventDisableTiming);
        cudaEventCreateWithFlags(&ev2, cudaEventDisableTiming);
        inited = 1;
    }

    k_prep<<<T, 256>>>(temb, toks);
    k_gemm1<<<N / 128, 512, SM1>>>(Dx, out);

    // fork: gemm2 (rho) runs concurrently with the astar->y->u->vstar chain
    cudaEventRecord(ev1, 0);
    cudaStreamWaitEvent(s2, ev1, 0);
    k_gemm2<<<N / 128, 512, SM2, s2>>>(out);
    cudaEventRecord(ev2, s2);

    k_astar_ln<<<1, 1024>>>();
    k_y<<<N / 8, 256>>>(Dy, out);
    k_u<<<D, 256>>>(E, out);
    k_vstar<<<1, D>>>(out);

    cudaStreamWaitEvent(0, ev2, 0);  // join
}

// round 11
// speedup vs baseline: 1.4012x; 1.0864x over previous
#include <cuda_runtime.h>
#include <cuda_fp16.h>
#include <math.h>

#define N 16384
#define D 256
#define T 128
#define LOG2_097 (-0.04394334758759706f)

typedef unsigned int u32;
typedef unsigned long long u64;

// ---------------- scratch ---------------------------------------------------
__device__ float  g_V[T * D];      // gathered token embeddings fp32 [t][d]
__device__ __half g_Vh[T * D];     // V hi fp16 [t][k]
__device__ __half g_Vl[T * D];     // V lo (residual) fp16 [t][k]
__device__ __half g_cV[D * T];     // (0.97^(T-s)*V[s][d]) single fp16 [d][s]
__device__ float  g_part2[128 * T];
__device__ float  g_lnA[D];
__device__ float  g_u[D];

// ---------------- helpers ----------------------------------------------------
__device__ __forceinline__ u32 s2u(const void* p) {
    u32 a;
    asm("{ .reg .u64 t; cvta.to.shared.u64 t, %1; cvt.u32.u64 %0, t; }" : "=r"(a) : "l"(p));
    return a;
}

#define LDSM_X4(r, addr)                                                        \
    asm volatile(                                                               \
        "ldmatrix.sync.aligned.m8n8.x4.shared.b16 {%0,%1,%2,%3}, [%4];"         \
        : "=r"((r)[0]), "=r"((r)[1]), "=r"((r)[2]), "=r"((r)[3])                \
        : "r"(addr))

__device__ __forceinline__ void mma16816(float* c, const u32* a, u32 b0, u32 b1) {
    asm volatile(
        "mma.sync.aligned.m16n8k16.row.col.f32.f16.f16.f32 "
        "{%0,%1,%2,%3}, {%4,%5,%6,%7}, {%8,%9}, {%0,%1,%2,%3};"
        : "+f"(c[0]), "+f"(c[1]), "+f"(c[2]), "+f"(c[3])
        : "r"(a[0]), "r"(a[1]), "r"(a[2]), "r"(a[3]), "r"(b0), "r"(b1));
}

// float4 -> 4 packed fp16 (u64)
__device__ __forceinline__ u64 to_h4(float4 v) {
    __half2 a = __floats2half2_rn(v.x, v.y);
    __half2 b = __floats2half2_rn(v.z, v.w);
    u32 ua = *(u32*)&a, ub = *(u32*)&b;
    return ((u64)ub << 32) | ua;
}

// ---------------- K1: gather + V splits + cV (fused prep) --------------------
__global__ __launch_bounds__(256) void k_prep(const float* __restrict__ temb,
                                              const int* __restrict__ toks) {
    int t = blockIdx.x, d = threadIdx.x;
    float v = temb[(size_t)toks[t] * D + d];
    g_V[t * D + d] = v;
    __half hv = __float2half_rn(v);
    g_Vh[t * D + d] = hv;
    g_Vl[t * D + d] = __float2half_rn(v - __half2float(hv));
    float c = exp2f((float)(T - t) * LOG2_097);
    g_cV[d * T + t] = __float2half_rn(c * v);
}

// ---------------- K2: FUSED GEMM1 + GEMM2 ------------------------------------
// Phase A: C[n][t] = sum_k Dx[n][k]*V[t][k] (fp16 2-pass)
// Epilogue: relu+cumsum -> Xs; x_f -> out; XT fp16 splits -> SMEM; dot partials.
// Phase B: rho[d][n] = sum_s cV[d][s]*XT[n][s] (fp16 2-pass) -> d_out.
#define PA1 36
#define PA2 68
__global__ __launch_bounds__(512) void k_gemm12(const float* __restrict__ Dx,
                                                float* __restrict__ out) {
    extern __shared__ char sm[];
    // phase A tiles (aliased later by Xs)
    const int S_A = 0, S_BH = 18432, S_BL = 36864;
    // epilogue: Xs [128][130] f32 @0..66560, sx @66560, tot @67072
    // phase B: XT hi/lo [128 n][68w], cV [256 d][68w]
    const int XBH = 69632, XBL = 104448, SCV = 139264;  // ends 208896
    int tid = threadIdx.x;
    int lane = tid & 31, wid = tid >> 5;  // 16 warps
    int gr = lane >> 2, gc = lane & 3;
    int r8 = lane & 7, sub = lane >> 3;
    int n0 = blockIdx.x * 128;
    u32 smb = s2u(sm);

    // ---- stage cV into SMEM (phase-B A operand; disjoint region) ----
#pragma unroll
    for (int r = 0; r < 8; r++) {
        int gi = tid + 512 * r;  // 4096 uint4
        int row = gi >> 4, j4 = gi & 15;
        *(uint4*)(sm + SCV + row * (PA2 * 4) + j4 * 16) = ((const uint4*)g_cV)[row * 16 + j4];
    }

    // ======================= PHASE A =======================
    {
        int m0w = (wid & 3) * 32;   // n rows
        int t0 = (wid >> 2) * 32;   // t cols

        float acc[2][4][4];
#pragma unroll
        for (int i = 0; i < 2; i++)
#pragma unroll
            for (int j = 0; j < 4; j++)
#pragma unroll
                for (int q = 0; q < 4; q++) acc[i][j][q] = 0.f;

        float4 pa[4];
        uint4 pbh[2], pbl[2];
#pragma unroll
        for (int r = 0; r < 4; r++) {
            int gi = tid + 512 * r;
            int row = gi >> 4, f4 = gi & 15;
            pa[r] = *(const float4*)&Dx[(size_t)(n0 + row) * D + f4 * 4];
        }
#pragma unroll
        for (int r = 0; r < 2; r++) {
            int gi = tid + 512 * r;
            int row = gi >> 3, j4 = gi & 7;
            pbh[r] = ((const uint4*)g_Vh)[row * 32 + j4];
            pbl[r] = ((const uint4*)g_Vl)[row * 32 + j4];
        }

        for (int c = 0; c < 4; c++) {  // K chunks of 64
#pragma unroll
            for (int r = 0; r < 4; r++) {
                int gi = tid + 512 * r;
                int row = gi >> 4, f4 = gi & 15;
                *(u64*)(sm + S_A + row * (PA1 * 4) + f4 * 8) = to_h4(pa[r]);
            }
#pragma unroll
            for (int r = 0; r < 2; r++) {
                int gi = tid + 512 * r;
                int row = gi >> 3, j4 = gi & 7;
                *(uint4*)(sm + S_BH + row * (PA1 * 4) + j4 * 16) = pbh[r];
                *(uint4*)(sm + S_BL + row * (PA1 * 4) + j4 * 16) = pbl[r];
            }
            __syncthreads();
            if (c < 3) {
#pragma unroll
                for (int r = 0; r < 4; r++) {
                    int gi = tid + 512 * r;
                    int row = gi >> 4, f4 = gi & 15;
                    pa[r] = *(const float4*)&Dx[(size_t)(n0 + row) * D + (c + 1) * 64 + f4 * 4];
                }
#pragma unroll
                for (int r = 0; r < 2; r++) {
                    int gi = tid + 512 * r;
                    int row = gi >> 3, j4 = gi & 7;
                    pbh[r] = ((const uint4*)g_Vh)[row * 32 + (c + 1) * 8 + j4];
                    pbl[r] = ((const uint4*)g_Vl)[row * 32 + (c + 1) * 8 + j4];
                }
            }
#pragma unroll
            for (int ks = 0; ks < 4; ks++) {
                u32 ah[2][4], bh[2][4], bl[2][4];
#pragma unroll
                for (int mt = 0; mt < 2; mt++) {
                    int aw = (m0w + mt * 16 + r8 + (sub & 1) * 8) * PA1 + (sub >> 1) * 4 + ks * 8;
                    LDSM_X4(ah[mt], smb + S_A + aw * 4);
                }
#pragma unroll
                for (int g = 0; g < 2; g++) {
                    int bw = (t0 + g * 16 + r8 + (sub >> 1) * 8) * PA1 + (sub & 1) * 4 + ks * 8;
                    LDSM_X4(bh[g], smb + S_BH + bw * 4);
                    LDSM_X4(bl[g], smb + S_BL + bw * 4);
                }
#pragma unroll
                for (int g = 0; g < 2; g++)
#pragma unroll
                    for (int mt = 0; mt < 2; mt++) {
                        mma16816(acc[mt][2 * g], ah[mt], bh[g][0], bh[g][1]);
                        mma16816(acc[mt][2 * g + 1], ah[mt], bh[g][2], bh[g][3]);
                    }
#pragma unroll
                for (int g = 0; g < 2; g++)
#pragma unroll
                    for (int mt = 0; mt < 2; mt++) {
                        mma16816(acc[mt][2 * g], ah[mt], bl[g][0], bl[g][1]);
                        mma16816(acc[mt][2 * g + 1], ah[mt], bl[g][2], bl[g][3]);
                    }
            }
            __syncthreads();
        }

        // ---- epilogue: relu -> Xs, cumsum, XT splits to SMEM, partials ----
        float* Xs = (float*)sm;
        float* sx = (float*)(sm + 66560);
        float* tot = (float*)(sm + 67072);
#pragma unroll
        for (int mt = 0; mt < 2; mt++)
#pragma unroll
            for (int j = 0; j < 4; j++) {
                int row = m0w + mt * 16 + gr;
                int col = t0 + j * 8 + 2 * gc;
                *(float2*)&Xs[row * 130 + col] =
                    make_float2(fmaxf(acc[mt][j][0], 0.f), fmaxf(acc[mt][j][1], 0.f));
                *(float2*)&Xs[(row + 8) * 130 + col] =
                    make_float2(fmaxf(acc[mt][j][2], 0.f), fmaxf(acc[mt][j][3], 0.f));
            }
        __syncthreads();
        {
            int n = tid & 127, q = tid >> 7;  // 4 t-segments of 32
            float v[32];
            float a = 0.f;
#pragma unroll
            for (int i = 0; i < 16; i++) {
                float2 p = *(float2*)&Xs[n * 130 + q * 32 + 2 * i];
                a += p.x;
                v[2 * i] = a;
                a += p.y;
                v[2 * i + 1] = a;
            }
            tot[n * 4 + q] = a;
            __syncthreads();
            float off = 0.f;
#pragma unroll
            for (int qq = 0; qq < 3; qq++)
                if (qq < q) off += tot[n * 4 + qq];
#pragma unroll
            for (int p = 0; p < 16; p++) {
                float x0 = v[2 * p] + off, x1 = v[2 * p + 1] + off;
                *(float2*)&Xs[n * 130 + q * 32 + 2 * p] = make_float2(x0, x1);
                __half2 hp = __floats2half2_rn(x0, x1);
                float r0 = x0 - __half2float(__low2half(hp));
                float r1 = x1 - __half2float(__high2half(hp));
                __half2 lp = __floats2half2_rn(r0, r1);
                int wc = q * 16 + p;  // word col (s/2)
                *(u32*)(sm + XBH + n * (PA2 * 4) + wc * 4) = *(u32*)&hp;
                *(u32*)(sm + XBL + n * (PA2 * 4) + wc * 4) = *(u32*)&lp;
            }
            if (q == 3) {
                float xf = v[31] + off;
                out[n0 + n] = xf;
                sx[n] = xf;
            }
        }
        __syncthreads();
        {
            int t = tid & 127, q = tid >> 7;  // 4 n-segments of 32
            float s = 0.f;
#pragma unroll 8
            for (int n2 = q * 32; n2 < q * 32 + 32; n2++)
                s = fmaf(Xs[n2 * 130 + t], sx[n2], s);
            tot[t * 4 + q] = s;
        }
        __syncthreads();
        if (tid < 128)
            g_part2[blockIdx.x * 128 + tid] =
                (tot[tid * 4] + tot[tid * 4 + 1]) + (tot[tid * 4 + 2] + tot[tid * 4 + 3]);
        __syncthreads();
    }

    // ======================= PHASE B =======================
    {
        int m0w = (wid & 7) * 32;   // d rows
        int nb = (wid >> 3) * 64;   // n cols within tile

        float acc[2][8][4];
#pragma unroll
        for (int i = 0; i < 2; i++)
#pragma unroll
            for (int j = 0; j < 8; j++)
#pragma unroll
                for (int q = 0; q < 4; q++) acc[i][j][q] = 0.f;

#pragma unroll
        for (int ks = 0; ks < 8; ks++) {
            u32 ah[2][4];
#pragma unroll
            for (int mt = 0; mt < 2; mt++) {
                int aw = (m0w + mt * 16 + r8 + (sub & 1) * 8) * PA2 + (sub >> 1) * 4 + ks * 8;
                LDSM_X4(ah[mt], smb + SCV + aw * 4);
            }
#pragma unroll
            for (int g = 0; g < 4; g++) {
                u32 bh[4], bl[4];
                int bw = (nb + g * 16 + r8 + (sub >> 1) * 8) * PA2 + (sub & 1) * 4 + ks * 8;
                LDSM_X4(bh, smb + XBH + bw * 4);
                LDSM_X4(bl, smb + XBL + bw * 4);
                mma16816(acc[0][2 * g], ah[0], bh[0], bh[1]);
                mma16816(acc[1][2 * g], ah[1], bh[0], bh[1]);
                mma16816(acc[0][2 * g + 1], ah[0], bh[2], bh[3]);
                mma16816(acc[1][2 * g + 1], ah[1], bh[2], bh[3]);
                mma16816(acc[0][2 * g], ah[0], bl[0], bl[1]);
                mma16816(acc[1][2 * g], ah[1], bl[0], bl[1]);
                mma16816(acc[0][2 * g + 1], ah[0], bl[2], bl[3]);
                mma16816(acc[1][2 * g + 1], ah[1], bl[2], bl[3]);
            }
        }

        float* rho = out + 2 * N + D;
#pragma unroll
        for (int mt = 0; mt < 2; mt++)
#pragma unroll
            for (int j = 0; j < 8; j++) {
                int d = m0w + mt * 16 + gr;
                int col = n0 + nb + j * 8 + 2 * gc;
                *(float2*)&rho[(size_t)d * N + col] = make_float2(acc[mt][j][0], acc[mt][j][1]);
                *(float2*)&rho[(size_t)(d + 8) * N + col] =
                    make_float2(acc[mt][j][2], acc[mt][j][3]);
            }
    }
}

// ---------------- K3: a*[d] -> layernorm -> g_lnA (1024 thr, high MLP) -------
__global__ __launch_bounds__(1024) void k_astar_ln() {
    __shared__ float p1[1024];
    __shared__ float gg[T];
    __shared__ float p2[1024];
    __shared__ float red[256];
    int tid = threadIdx.x;
    {
        int t = tid & 127, q = tid >> 7;
        float s = 0.f;
#pragma unroll
        for (int b = q * 16; b < q * 16 + 16; b++) s += g_part2[b * 128 + t];
        p1[q * 128 + t] = s;
    }
    __syncthreads();
    if (tid < T) {
        float s = 0.f;
#pragma unroll
        for (int q = 0; q < 8; q++) s += p1[q * 128 + tid];
        float c = exp2f((float)(T - 1 - tid) * LOG2_097);
        gg[tid] = (tid < T - 1) ? c * s : 0.f;
    }
    __syncthreads();
    {
        int d = tid & 255, q = tid >> 8;
        float a = 0.f;
#pragma unroll
        for (int i = 0; i < 32; i++) {
            int s = q * 32 + i;
            a = fmaf(gg[s], g_V[s * D + d], a);
        }
        p2[q * 256 + d] = a;
    }
    __syncthreads();
    float a = 0.f;
    if (tid < 256) {
        a = (p2[tid] + p2[256 + tid]) + (p2[512 + tid] + p2[768 + tid]);
        red[tid] = a;
    }
    __syncthreads();
    for (int off = 128; off > 0; off >>= 1) {
        if (tid < off) red[tid] += red[tid + off];
        __syncthreads();
    }
    float m = red[0] * (1.f / D);
    __syncthreads();
    float ctr = a - m;
    if (tid < 256) red[tid] = ctr * ctr;
    __syncthreads();
    for (int off = 128; off > 0; off >>= 1) {
        if (tid < off) red[tid] += red[tid + off];
        __syncthreads();
    }
    if (tid < 256) {
        float sd = sqrtf(red[0] / (float)(D - 1));
        g_lnA[tid] = ctr / (sd + 1e-6f);
    }
}

// ---------------- K4: y[n] = relu(Dy.lnA) * relu(x_f) -> out[N:2N) ----------
__global__ void k_y(const float* __restrict__ Dy, float* __restrict__ out) {
    __shared__ float sa[D];
    int tid = threadIdx.x;
    sa[tid] = g_lnA[tid];
    __syncthreads();
    int warp = tid >> 5, lane = tid & 31;
    int n = blockIdx.x * 8 + warp;
    const float4* row = (const float4*)&Dy[(size_t)n * D];
    float s = 0.f;
#pragma unroll
    for (int r = 0; r < 2; r++) {
        float4 v = row[lane + 32 * r];
        int d = 4 * (lane + 32 * r);
        s = fmaf(v.x, sa[d], s);
        s = fmaf(v.y, sa[d + 1], s);
        s = fmaf(v.z, sa[d + 2], s);
        s = fmaf(v.w, sa[d + 3], s);
    }
#pragma unroll
    for (int off = 16; off > 0; off >>= 1) s += __shfl_down_sync(0xffffffffu, s, off);
    if (lane == 0) out[N + n] = fmaxf(s, 0.f) * fmaxf(out[n], 0.f);
}

// ---------------- K5: u[d] = E[d,:].y ---------------------------------------
__global__ void k_u(const float* __restrict__ E, const float* __restrict__ out) {
    __shared__ float red[256];
    int d = blockIdx.x, tid = threadIdx.x;
    const float4* e = (const float4*)&E[(size_t)d * N];
    const float4* y = (const float4*)&out[N];
    float s = 0.f;
#pragma unroll 4
    for (int r = 0; r < 16; r++) {
        float4 a = e[tid + 256 * r];
        float4 b = y[tid + 256 * r];
        s = fmaf(a.x, b.x, s);
        s = fmaf(a.y, b.y, s);
        s = fmaf(a.z, b.z, s);
        s = fmaf(a.w, b.w, s);
    }
    red[tid] = s;
    __syncthreads();
    for (int off = 128; off > 0; off >>= 1) {
        if (tid < off) red[tid] += red[tid + off];
        __syncthreads();
    }
    if (tid == 0) g_u[d] = red[0];
}

// ---------------- K6: v* = layernorm(u) -> out[2N:2N+D) ---------------------
__global__ void k_vstar(float* __restrict__ out) {
    __shared__ float red[256];
    int tid = threadIdx.x;
    float a = g_u[tid];
    red[tid] = a;
    __syncthreads();
    for (int off = 128; off > 0; off >>= 1) {
        if (tid < off) red[tid] += red[tid + off];
        __syncthreads();
    }
    float m = red[0] * (1.f / D);
    __syncthreads();
    float c = a - m;
    red[tid] = c * c;
    __syncthreads();
    for (int off = 128; off > 0; off >>= 1) {
        if (tid < off) red[tid] += red[tid + off];
        __syncthreads();
    }
    float sd = sqrtf(red[0] / (float)(D - 1));
    out[2 * N + tid] = c / (sd + 1e-6f);
}

// ---------------------------------------------------------------------------
extern "C" void kernel_launch(void* const* d_in, const int* in_sizes, int n_in,
                              void* d_out, int out_size) {
    const float* E    = (const float*)d_in[0];
    const float* Dx   = (const float*)d_in[1];
    const float* Dy   = (const float*)d_in[2];
    const float* temb = (const float*)d_in[3];
    const int*   toks = (const int*)d_in[4];
    float* out = (float*)d_out;

    const int SM12 = 208896;  // phaseA/Xs 69120 | XT hi/lo 69632 | cV 69632
    static int inited = 0;
    if (!inited) {
        cudaFuncSetAttribute(k_gemm12, cudaFuncAttributeMaxDynamicSharedMemorySize, SM12);
        inited = 1;
    }

    k_prep<<<T, 256>>>(temb, toks);
    k_gemm12<<<N / 128, 512, SM12>>>(Dx, out);
    k_astar_ln<<<1, 1024>>>();
    k_y<<<N / 8, 256>>>(Dy, out);
    k_u<<<D, 256>>>(E, out);
    k_vstar<<<1, D>>>(out);
}